// round 6
// baseline (speedup 1.0000x reference)
#include <cuda_runtime.h>
#include <math.h>

#define BQ 16
#define NQ 4096
#define SQ 1024
#define KQ 32
#define CQ 64
#define HQ 128
#define CAND_CAP 768
#define FS 132        // Fbuf stride (words)

__device__ int g_group_idx[BQ * SQ * KQ];

// weights pre-packed as per-thread MMA B-fragments: uint2{b0,b1} at
// index (kt*128 + n)*4 + tg, where b0=W[kt*8+tg][n], b1=W[kt*8+4+tg][n]
__device__ uint2 g_W1p[9  * 512];
__device__ uint2 g_W2p[16 * 512];
__device__ uint2 g_W3p[17 * 512];
__device__ uint2 g_W4p[16 * 512];

__device__ __forceinline__ unsigned f2tf(float f) {
    unsigned r; asm("cvt.rna.tf32.f32 %0, %1;" : "=r"(r) : "f"(f)); return r;
}
__device__ __forceinline__ void mma_tf32(
    float& d0, float& d1, float& d2, float& d3,
    unsigned a0, unsigned a1, unsigned a2, unsigned a3,
    unsigned b0, unsigned b1)
{
    asm("mma.sync.aligned.m16n8k8.row.col.f32.tf32.tf32.f32 "
        "{%0,%1,%2,%3}, {%4,%5,%6,%7}, {%8,%9}, {%0,%1,%2,%3};"
        : "+f"(d0), "+f"(d1), "+f"(d2), "+f"(d3)
        : "r"(a0), "r"(a1), "r"(a2), "r"(a3), "r"(b0), "r"(b1));
}

// fragment-major A index (word): P[kt][mi][ls][reg], ls = (c&3)*8 + (r&7),
// reg = ((r>>3)&1) + 2*((c>>2)&1). Thread (g,tg) reads LDS.128 at ls=tg*8+g.
__device__ __forceinline__ int pidx(int r, int c) {
    int kt = c >> 3, mi = r >> 4;
    int ls = (c & 3) * 8 + (r & 7);
    int reg = ((r >> 3) & 1) + 2 * ((c >> 2) & 1);
    return (((kt * 4 + mi) * 32 + ls) << 2) + reg;
}

// ---------------------------------------------------------------------------
// Kernel 0: convert + pack weights into per-thread tf32 B-fragments.
// ---------------------------------------------------------------------------
__device__ __forceinline__ void pack_w(int i, int KT, int Kreal,
                                       const float* __restrict__ W, uint2* out)
{
    if (i < KT * 512) {
        int kt = i >> 9, rem = i & 511, n = rem >> 2, tg = rem & 3;
        int k0 = kt * 8 + tg;
        float w0 = (k0     < Kreal) ? W[k0 * 128 + n]       : 0.f;
        float w1 = (k0 + 4 < Kreal) ? W[(k0 + 4) * 128 + n] : 0.f;
        out[i] = make_uint2(f2tf(w0), f2tf(w1));
    }
}
__global__ void cvt_w_kernel(const float* __restrict__ W1,
                             const float* __restrict__ W2,
                             const float* __restrict__ W3,
                             const float* __restrict__ W4)
{
    int i = blockIdx.x * 256 + threadIdx.x;
    pack_w(i, 9,  67,  W1, g_W1p);
    pack_w(i, 16, 128, W2, g_W2p);
    pack_w(i, 17, 131, W3, g_W3p);
    pack_w(i, 16, 128, W4, g_W4p);
}

// ---------------------------------------------------------------------------
// Kernel 1: FPS (unchanged from R5).
// ---------------------------------------------------------------------------
__global__ __launch_bounds__(512) void fps_kernel(
    const float* __restrict__ xyz, float* __restrict__ new_xyz)
{
    const int b = blockIdx.x;
    const int t = threadIdx.x;
    const int lane = t & 31;
    const int warp = t >> 5;
    extern __shared__ float sm[];
    float* xs = sm;
    float* ys = sm + NQ;
    float* zs = sm + 2 * NQ;
    __shared__ unsigned sv[2][16];
    __shared__ int      si[2][16];

    const float* xb = xyz + (size_t)b * NQ * 3;
    for (int idx = t; idx < NQ * 3; idx += 512) {
        float v = xb[idx];
        int p = idx / 3;
        int j = idx - 3 * p;
        if (j == 0) xs[p] = v; else if (j == 1) ys[p] = v; else zs[p] = v;
    }
    __syncthreads();

    float px[8], py[8], pz[8], dmin[8];
#pragma unroll
    for (int r = 0; r < 8; r++) {
        int p = t + (r << 9);
        px[r] = xs[p]; py[r] = ys[p]; pz[r] = zs[p];
        dmin[r] = 3.0e38f;
    }
    float cx = xs[0], cy = ys[0], cz = zs[0];
    if (t == 0) {
        float* o = &new_xyz[(size_t)b * SQ * 3];
        o[0] = cx; o[1] = cy; o[2] = cz;
    }

    for (int i = 1; i < SQ; i++) {
        unsigned bv = 0; int bi = 0x7fffffff;
#pragma unroll
        for (int r = 0; r < 8; r++) {
            float dx = px[r] - cx, dy = py[r] - cy, dz = pz[r] - cz;
            float d = dx * dx;
            d = fmaf(dy, dy, d);
            d = fmaf(dz, dz, d);
            float dm = dmin[r];
            dm = d < dm ? d : dm;
            dmin[r] = dm;
            unsigned bits = __float_as_uint(dm);
            if (bits > bv) { bv = bits; bi = t + (r << 9); }
        }
        unsigned vmax = __reduce_max_sync(0xffffffffu, bv);
        int cnd = (bv == vmax) ? bi : 0x7fffffff;
        int imin = __reduce_min_sync(0xffffffffu, cnd);
        const int buf = i & 1;
        if (lane == 0) { sv[buf][warp] = vmax; si[buf][warp] = imin; }
        __syncthreads();
        unsigned vb = sv[buf][lane & 15];
        int      ib = si[buf][lane & 15];
        unsigned vm = __reduce_max_sync(0xffffffffu, vb);
        int c2 = (vb == vm) ? ib : 0x7fffffff;
        int im = __reduce_min_sync(0xffffffffu, c2);
        cx = xs[im]; cy = ys[im]; cz = zs[im];
        if (t == 0) {
            float* o = &new_xyz[((size_t)b * SQ + i) * 3];
            o[0] = cx; o[1] = cy; o[2] = cz;
        }
    }
}

// ---------------------------------------------------------------------------
// Kernel 2: ball query (unchanged).
// ---------------------------------------------------------------------------
__global__ __launch_bounds__(256) void ball_kernel(
    const float* __restrict__ xyz, const float* __restrict__ new_xyz)
{
    const int blk = blockIdx.x;
    const int b = blk >> 7;
    const int t = threadIdx.x;
    const int lane = t & 31;
    const int warp = t >> 5;
    const int s = ((blk & 127) << 3) + warp;

    extern __shared__ float sm[];
    float* xs = sm;
    float* ys = sm + NQ;
    float* zs = sm + 2 * NQ;
    unsigned long long* cand =
        (unsigned long long*)(sm + 3 * NQ) + (size_t)warp * CAND_CAP;

    const float* xb = xyz + (size_t)b * NQ * 3;
    for (int idx = t; idx < NQ * 3; idx += 256) {
        float v = xb[idx];
        int p = idx / 3;
        int j = idx - 3 * p;
        if (j == 0) xs[p] = v; else if (j == 1) ys[p] = v; else zs[p] = v;
    }
    __syncthreads();

    const float* cc = &new_xyz[((size_t)b * SQ + s) * 3];
    const float cx = cc[0], cy = cc[1], cz = cc[2];

    int cnt = 0;
#pragma unroll 4
    for (int j = 0; j < NQ / 32; j++) {
        int p = (j << 5) + lane;
        float dx = xs[p] - cx, dy = ys[p] - cy, dz = zs[p] - cz;
        float d = dx * dx;
        d = fmaf(dy, dy, d);
        d = fmaf(dz, dz, d);
        bool in = (d <= 0.04f);
        unsigned m = __ballot_sync(0xffffffffu, in);
        int pos = cnt + __popc(m & ((1u << lane) - 1u));
        if (in && pos < CAND_CAP)
            cand[pos] = ((unsigned long long)__float_as_uint(d) << 32) |
                        (unsigned)p;
        cnt += __popc(m);
    }
    __syncwarp();
    int L = cnt < CAND_CAP ? cnt : CAND_CAP;

    int* go = &g_group_idx[((size_t)b * SQ + s) * KQ];

    for (int c = lane; c < L; c += 32) {
        unsigned long long key = cand[c];
        int rank = 0;
        for (int j = 0; j < L; j++) rank += (cand[j] < key);
        if (rank < KQ) go[rank] = (int)(unsigned)key;
    }

    if (L < KQ) {
        int fillpos = L;
        for (int base = 0; base < NQ && fillpos < KQ; base += 32) {
            int p = base + lane;
            float dx = xs[p] - cx, dy = ys[p] - cy, dz = zs[p] - cz;
            float d = dx * dx;
            d = fmaf(dy, dy, d);
            d = fmaf(dz, dz, d);
            bool ob = (d > 0.04f);
            unsigned m = __ballot_sync(0xffffffffu, ob);
            int pos = fillpos + __popc(m & ((1u << lane) - 1u));
            if (ob && pos < KQ) go[pos] = p;
            fillpos += __popc(m);
        }
    }
}

// ---------------------------------------------------------------------------
// Kernel 3: fused MLP; fragment-major A (LDS.128) + packed B (LDG.64).
// 2 centers/block (M=64), 4 warps x 32 channels.
// ---------------------------------------------------------------------------
template<int KT>
__device__ __forceinline__ void gemm_layer(
    const unsigned* __restrict__ P, const uint2* __restrict__ Wp,
    int g, int tg, int nb, float acc[4][4][4])
{
#pragma unroll
    for (int mi = 0; mi < 4; mi++)
#pragma unroll
        for (int nt = 0; nt < 4; nt++)
#pragma unroll
            for (int q = 0; q < 4; q++) acc[mi][nt][q] = 0.f;

    const int ls = tg * 8 + g;
#pragma unroll
    for (int kt = 0; kt < KT; kt++) {
        uint4 a[4];
#pragma unroll
        for (int mi = 0; mi < 4; mi++)
            a[mi] = *(const uint4*)&P[(((kt * 4 + mi) * 32 + ls) << 2)];
#pragma unroll
        for (int nt = 0; nt < 4; nt++) {
            int nc = nb + (nt << 3) + g;
            uint2 bb = __ldg(&Wp[(kt * 128 + nc) * 4 + tg]);
#pragma unroll
            for (int mi = 0; mi < 4; mi++)
                mma_tf32(acc[mi][nt][0], acc[mi][nt][1],
                         acc[mi][nt][2], acc[mi][nt][3],
                         a[mi].x, a[mi].y, a[mi].z, a[mi].w, bb.x, bb.y);
        }
    }
}

__global__ __launch_bounds__(128) void mlp_kernel(
    const float* __restrict__ xyz, const float* __restrict__ feats,
    const float* __restrict__ new_xyz,
    const float* __restrict__ b1, const float* __restrict__ b2,
    const float* __restrict__ b3, const float* __restrict__ b4,
    float* __restrict__ f_out)
{
    const int bs0 = blockIdx.x << 1;
    const int b   = bs0 >> 10;
    const int t   = threadIdx.x;
    const int lane = t & 31;
    const int warp = t >> 5;
    const int g  = lane >> 2;
    const int tg = lane & 3;
    const int nb = warp << 5;

    extern __shared__ unsigned dynsm[];
    unsigned* P    = dynsm;                       // 17*4*32*4 = 8704 words
    float*    Fbuf = (float*)(dynsm + 8704);      // 64*FS = 8448 words
    float*    xns  = Fbuf + 64 * FS;              // 192
    float*    mb   = xns + 192;                   // 256 means (2 centers x 128)
    __shared__ int   gi[2 * KQ];
    __shared__ float ctr[6];

    if (t < 2 * KQ) gi[t] = g_group_idx[(size_t)bs0 * KQ + t];
    if (t >= 64 && t < 70) ctr[t - 64] = new_xyz[(size_t)bs0 * 3 + (t - 64)];
    __syncthreads();

    // ---- gather into fragment-major P: c0-2 xn, c3-66 feats, c67-71 zero ----
    const float* fb = feats + (size_t)b * NQ * CQ;
    for (int e = t; e < 32 * CQ; e += 128) {              // row-pairs x channels
        int pr = e >> 6, ch = e & 63;
        int r = ((pr >> 3) << 4) + (pr & 7);
        float v0 = fb[(size_t)gi[r] * CQ + ch];
        float v8 = fb[(size_t)gi[r + 8] * CQ + ch];
        *(uint2*)&P[pidx(r, ch + 3)] = make_uint2(f2tf(v0), f2tf(v8));
    }
    if (t < 96) {                                          // xn
        int pr = t / 3, j = t % 3;
        int r = ((pr >> 3) << 4) + (pr & 7);
        int cen = r >> 5;
        float v0 = xyz[((size_t)b * NQ + gi[r]) * 3 + j]     - ctr[cen * 3 + j];
        float v8 = xyz[((size_t)b * NQ + gi[r + 8]) * 3 + j] - ctr[cen * 3 + j];
        xns[cen * 96 + j * 32 + (r & 31)]       = v0;
        xns[cen * 96 + j * 32 + ((r + 8) & 31)] = v8;
        *(uint2*)&P[pidx(r, j)] = make_uint2(f2tf(v0), f2tf(v8));
    }
    for (int e = t; e < 160; e += 128) {                   // zero pad c67..71
        int pr = e / 5, c = 67 + e % 5;
        int r = ((pr >> 3) << 4) + (pr & 7);
        *(uint2*)&P[pidx(r, c)] = make_uint2(0u, 0u);
    }
    __syncthreads();

    float acc[4][4][4];

    // ----- Layer 1: 72(pad) -> 128, relu -----
    gemm_layer<9>(P, g_W1p, g, tg, nb, acc);
    __syncthreads();
#pragma unroll
    for (int nt = 0; nt < 4; nt++) {
        int cc = nb + (nt << 3) + 2 * tg;
        float bb0 = __ldg(&b1[cc]), bb1 = __ldg(&b1[cc + 1]);
#pragma unroll
        for (int mi = 0; mi < 4; mi++) {
            int r = mi * 16 + g;
            *(uint2*)&P[pidx(r, cc)] = make_uint2(
                f2tf(fmaxf(acc[mi][nt][0] + bb0, 0.f)),
                f2tf(fmaxf(acc[mi][nt][2] + bb0, 0.f)));
            *(uint2*)&P[pidx(r, cc + 1)] = make_uint2(
                f2tf(fmaxf(acc[mi][nt][1] + bb1, 0.f)),
                f2tf(fmaxf(acc[mi][nt][3] + bb1, 0.f)));
        }
    }
    __syncthreads();

    // ----- Layer 2: 128 -> 128, relu -> Fbuf (fp32) -----
    gemm_layer<16>(P, g_W2p, g, tg, nb, acc);
#pragma unroll
    for (int nt = 0; nt < 4; nt++) {
        int cc = nb + (nt << 3) + 2 * tg;
        float bb0 = __ldg(&b2[cc]), bb1 = __ldg(&b2[cc + 1]);
#pragma unroll
        for (int mi = 0; mi < 4; mi++) {
            int r0 = mi * 16 + g;
            Fbuf[r0 * FS + cc]           = fmaxf(acc[mi][nt][0] + bb0, 0.f);
            Fbuf[r0 * FS + cc + 1]       = fmaxf(acc[mi][nt][1] + bb1, 0.f);
            Fbuf[(r0 + 8) * FS + cc]     = fmaxf(acc[mi][nt][2] + bb0, 0.f);
            Fbuf[(r0 + 8) * FS + cc + 1] = fmaxf(acc[mi][nt][3] + bb1, 0.f);
        }
    }
    __syncthreads();

    // ---- means per center/channel ----
    {
        float m0 = 0.f, m1 = 0.f;
#pragma unroll 8
        for (int r = 0; r < 32; r++) {
            m0 += Fbuf[r * FS + t];
            m1 += Fbuf[(r + 32) * FS + t];
        }
        mb[t]       = m0 * (1.f / 32.f);
        mb[128 + t] = m1 * (1.f / 32.f);
    }
    __syncthreads();

    // ---- A2 into P: c0-2 xn, c3-130 f'-mean, c131-135 zero ----
#pragma unroll
    for (int nt = 0; nt < 4; nt++) {
        int cc = nb + (nt << 3) + 2 * tg;
#pragma unroll
        for (int mi = 0; mi < 4; mi++) {
            int r = mi * 16 + g;
            int cen = mi >> 1;
            float mc0 = mb[cen * 128 + cc], mc1 = mb[cen * 128 + cc + 1];
            *(uint2*)&P[pidx(r, cc + 3)] = make_uint2(
                f2tf(Fbuf[r * FS + cc] - mc0),
                f2tf(Fbuf[(r + 8) * FS + cc] - mc0));
            *(uint2*)&P[pidx(r, cc + 4)] = make_uint2(
                f2tf(Fbuf[r * FS + cc + 1] - mc1),
                f2tf(Fbuf[(r + 8) * FS + cc + 1] - mc1));
        }
    }
    if (t < 96) {
        int pr = t / 3, j = t % 3;
        int r = ((pr >> 3) << 4) + (pr & 7);
        int cen = r >> 5;
        float v0 = xns[cen * 96 + j * 32 + (r & 31)];
        float v8 = xns[cen * 96 + j * 32 + ((r + 8) & 31)];
        *(uint2*)&P[pidx(r, j)] = make_uint2(f2tf(v0), f2tf(v8));
    }
    for (int e = t; e < 160; e += 128) {
        int pr = e / 5, c = 131 + e % 5;
        int r = ((pr >> 3) << 4) + (pr & 7);
        *(uint2*)&P[pidx(r, c)] = make_uint2(0u, 0u);
    }
    __syncthreads();

    // ----- Layer 3: 136(pad) -> 128, relu -----
    gemm_layer<17>(P, g_W3p, g, tg, nb, acc);
    __syncthreads();
#pragma unroll
    for (int nt = 0; nt < 4; nt++) {
        int cc = nb + (nt << 3) + 2 * tg;
        float bb0 = __ldg(&b3[cc]), bb1 = __ldg(&b3[cc + 1]);
#pragma unroll
        for (int mi = 0; mi < 4; mi++) {
            int r = mi * 16 + g;
            *(uint2*)&P[pidx(r, cc)] = make_uint2(
                f2tf(fmaxf(acc[mi][nt][0] + bb0, 0.f)),
                f2tf(fmaxf(acc[mi][nt][2] + bb0, 0.f)));
            *(uint2*)&P[pidx(r, cc + 1)] = make_uint2(
                f2tf(fmaxf(acc[mi][nt][1] + bb1, 0.f)),
                f2tf(fmaxf(acc[mi][nt][3] + bb1, 0.f)));
        }
    }
    __syncthreads();

    // ----- Layer 4: 128 -> 128, sigmoid; weighted sum per center -----
    gemm_layer<16>(P, g_W4p, g, tg, nb, acc);
#pragma unroll
    for (int nt = 0; nt < 4; nt++) {
        int cc = nb + (nt << 3) + 2 * tg;
        float bb0 = __ldg(&b4[cc]), bb1 = __ldg(&b4[cc + 1]);
        float s0[2] = {0.f, 0.f}, s1[2] = {0.f, 0.f};
#pragma unroll
        for (int mi = 0; mi < 4; mi++) {
            int c = mi >> 1;
            int r0 = mi * 16 + g;
            float a0 = 1.f / (1.f + __expf(-(acc[mi][nt][0] + bb0)));
            float a1 = 1.f / (1.f + __expf(-(acc[mi][nt][1] + bb1)));
            float a2 = 1.f / (1.f + __expf(-(acc[mi][nt][2] + bb0)));
            float a3 = 1.f / (1.f + __expf(-(acc[mi][nt][3] + bb1)));
            s0[c] = fmaf(a0, Fbuf[r0 * FS + cc], s0[c]);
            s1[c] = fmaf(a1, Fbuf[r0 * FS + cc + 1], s1[c]);
            s0[c] = fmaf(a2, Fbuf[(r0 + 8) * FS + cc], s0[c]);
            s1[c] = fmaf(a3, Fbuf[(r0 + 8) * FS + cc + 1], s1[c]);
        }
#pragma unroll
        for (int off = 4; off < 32; off <<= 1) {
            s0[0] += __shfl_xor_sync(0xffffffffu, s0[0], off);
            s1[0] += __shfl_xor_sync(0xffffffffu, s1[0], off);
            s0[1] += __shfl_xor_sync(0xffffffffu, s0[1], off);
            s1[1] += __shfl_xor_sync(0xffffffffu, s1[1], off);
        }
        if (g == 0) {
            f_out[(size_t)bs0 * HQ + cc]           = s0[0];
            f_out[(size_t)bs0 * HQ + cc + 1]       = s1[0];
            f_out[((size_t)bs0 + 1) * HQ + cc]     = s0[1];
            f_out[((size_t)bs0 + 1) * HQ + cc + 1] = s1[1];
        }
    }
}

// ---------------------------------------------------------------------------
extern "C" void kernel_launch(void* const* d_in, const int* in_sizes, int n_in,
                              void* d_out, int out_size)
{
    const float* xyz   = (const float*)d_in[0];
    const float* feats = (const float*)d_in[1];
    const float* W1 = (const float*)d_in[2];
    const float* b1 = (const float*)d_in[3];
    const float* W2 = (const float*)d_in[4];
    const float* b2 = (const float*)d_in[5];
    const float* W3 = (const float*)d_in[6];
    const float* b3 = (const float*)d_in[7];
    const float* W4 = (const float*)d_in[8];
    const float* b4 = (const float*)d_in[9];

    float* out     = (float*)d_out;
    float* new_xyz = out;
    float* f_out   = out + (size_t)BQ * SQ * 3;

    const int fps_smem  = 3 * NQ * sizeof(float);                       // 48KB
    const int ball_smem = fps_smem + 8 * CAND_CAP * sizeof(long long);  // 96KB
    const int mlp_smem  = (8704 + 64 * FS + 192 + 256) * 4;             // ~69KB
    cudaFuncSetAttribute(fps_kernel,
                         cudaFuncAttributeMaxDynamicSharedMemorySize, fps_smem);
    cudaFuncSetAttribute(ball_kernel,
                         cudaFuncAttributeMaxDynamicSharedMemorySize, ball_smem);
    cudaFuncSetAttribute(mlp_kernel,
                         cudaFuncAttributeMaxDynamicSharedMemorySize, mlp_smem);

    cvt_w_kernel<<<(17 * 512 + 255) / 256, 256>>>(W1, W2, W3, W4);
    fps_kernel <<<BQ, 512, fps_smem>>>(xyz, new_xyz);
    ball_kernel<<<(BQ * SQ) / 8, 256, ball_smem>>>(xyz, new_xyz);
    mlp_kernel <<<(BQ * SQ) / 2, 128, mlp_smem>>>(xyz, feats, new_xyz,
                                                  b1, b2, b3, b4, f_out);
}

// round 7
// speedup vs baseline: 1.2357x; 1.2357x over previous
#include <cuda_runtime.h>
#include <math.h>

#define BQ 16
#define NQ 4096
#define SQ 1024
#define KQ 32
#define CQ 64
#define HQ 128
#define CAND_CAP 768
#define FS 132        // Fbuf stride (words)

__device__ int g_group_idx[BQ * SQ * KQ];

// weights pre-packed as per-thread MMA B-fragments: uint2{b0,b1} at
// index (kt*128 + n)*4 + tg, where b0=W[kt*8+tg][n], b1=W[kt*8+4+tg][n]
__device__ uint2 g_W1p[9  * 512];
__device__ uint2 g_W2p[16 * 512];
__device__ uint2 g_W3p[17 * 512];
__device__ uint2 g_W4p[16 * 512];

__device__ __forceinline__ unsigned f2tf(float f) {
    unsigned r; asm("cvt.rna.tf32.f32 %0, %1;" : "=r"(r) : "f"(f)); return r;
}
__device__ __forceinline__ void mma_tf32(
    float& d0, float& d1, float& d2, float& d3,
    unsigned a0, unsigned a1, unsigned a2, unsigned a3,
    unsigned b0, unsigned b1)
{
    asm("mma.sync.aligned.m16n8k8.row.col.f32.tf32.tf32.f32 "
        "{%0,%1,%2,%3}, {%4,%5,%6,%7}, {%8,%9}, {%0,%1,%2,%3};"
        : "+f"(d0), "+f"(d1), "+f"(d2), "+f"(d3)
        : "r"(a0), "r"(a1), "r"(a2), "r"(a3), "r"(b0), "r"(b1));
}

// fragment-major A index (word): chunk = (kt*4+mi)*32 + ls, ls = OWNER LANE
// = (r&7)*4 + (c&3); reg = ((r>>3)&1) + 2*((c>>2)&1).
// Reader (g,tg) does one LDS.128 at ls = g*4+tg = lane -> conflict-free
// (quarter-warp lanes have distinct ls&7 -> distinct 128B offset groups).
__device__ __forceinline__ int pidx(int r, int c) {
    int kt = c >> 3, mi = r >> 4;
    int ls = (r & 7) * 4 + (c & 3);
    int reg = ((r >> 3) & 1) + 2 * ((c >> 2) & 1);
    return (((kt * 4 + mi) * 32 + ls) << 2) + reg;
}

// ---------------------------------------------------------------------------
// Kernel 0: convert + pack weights into per-thread tf32 B-fragments.
// ---------------------------------------------------------------------------
__device__ __forceinline__ void pack_w(int i, int KT, int Kreal,
                                       const float* __restrict__ W, uint2* out)
{
    if (i < KT * 512) {
        int kt = i >> 9, rem = i & 511, n = rem >> 2, tg = rem & 3;
        int k0 = kt * 8 + tg;
        float w0 = (k0     < Kreal) ? W[k0 * 128 + n]       : 0.f;
        float w1 = (k0 + 4 < Kreal) ? W[(k0 + 4) * 128 + n] : 0.f;
        out[i] = make_uint2(f2tf(w0), f2tf(w1));
    }
}
__global__ void cvt_w_kernel(const float* __restrict__ W1,
                             const float* __restrict__ W2,
                             const float* __restrict__ W3,
                             const float* __restrict__ W4)
{
    int i = blockIdx.x * 256 + threadIdx.x;
    pack_w(i, 9,  67,  W1, g_W1p);
    pack_w(i, 16, 128, W2, g_W2p);
    pack_w(i, 17, 131, W3, g_W3p);
    pack_w(i, 16, 128, W4, g_W4p);
}

// ---------------------------------------------------------------------------
// Kernel 1: FPS (unchanged).
// ---------------------------------------------------------------------------
__global__ __launch_bounds__(512) void fps_kernel(
    const float* __restrict__ xyz, float* __restrict__ new_xyz)
{
    const int b = blockIdx.x;
    const int t = threadIdx.x;
    const int lane = t & 31;
    const int warp = t >> 5;
    extern __shared__ float sm[];
    float* xs = sm;
    float* ys = sm + NQ;
    float* zs = sm + 2 * NQ;
    __shared__ unsigned sv[2][16];
    __shared__ int      si[2][16];

    const float* xb = xyz + (size_t)b * NQ * 3;
    for (int idx = t; idx < NQ * 3; idx += 512) {
        float v = xb[idx];
        int p = idx / 3;
        int j = idx - 3 * p;
        if (j == 0) xs[p] = v; else if (j == 1) ys[p] = v; else zs[p] = v;
    }
    __syncthreads();

    float px[8], py[8], pz[8], dmin[8];
#pragma unroll
    for (int r = 0; r < 8; r++) {
        int p = t + (r << 9);
        px[r] = xs[p]; py[r] = ys[p]; pz[r] = zs[p];
        dmin[r] = 3.0e38f;
    }
    float cx = xs[0], cy = ys[0], cz = zs[0];
    if (t == 0) {
        float* o = &new_xyz[(size_t)b * SQ * 3];
        o[0] = cx; o[1] = cy; o[2] = cz;
    }

    for (int i = 1; i < SQ; i++) {
        unsigned bv = 0; int bi = 0x7fffffff;
#pragma unroll
        for (int r = 0; r < 8; r++) {
            float dx = px[r] - cx, dy = py[r] - cy, dz = pz[r] - cz;
            float d = dx * dx;
            d = fmaf(dy, dy, d);
            d = fmaf(dz, dz, d);
            float dm = dmin[r];
            dm = d < dm ? d : dm;
            dmin[r] = dm;
            unsigned bits = __float_as_uint(dm);
            if (bits > bv) { bv = bits; bi = t + (r << 9); }
        }
        unsigned vmax = __reduce_max_sync(0xffffffffu, bv);
        int cnd = (bv == vmax) ? bi : 0x7fffffff;
        int imin = __reduce_min_sync(0xffffffffu, cnd);
        const int buf = i & 1;
        if (lane == 0) { sv[buf][warp] = vmax; si[buf][warp] = imin; }
        __syncthreads();
        unsigned vb = sv[buf][lane & 15];
        int      ib = si[buf][lane & 15];
        unsigned vm = __reduce_max_sync(0xffffffffu, vb);
        int c2 = (vb == vm) ? ib : 0x7fffffff;
        int im = __reduce_min_sync(0xffffffffu, c2);
        cx = xs[im]; cy = ys[im]; cz = zs[im];
        if (t == 0) {
            float* o = &new_xyz[((size_t)b * SQ + i) * 3];
            o[0] = cx; o[1] = cy; o[2] = cz;
        }
    }
}

// ---------------------------------------------------------------------------
// Kernel 2: ball query (unchanged).
// ---------------------------------------------------------------------------
__global__ __launch_bounds__(256) void ball_kernel(
    const float* __restrict__ xyz, const float* __restrict__ new_xyz)
{
    const int blk = blockIdx.x;
    const int b = blk >> 7;
    const int t = threadIdx.x;
    const int lane = t & 31;
    const int warp = t >> 5;
    const int s = ((blk & 127) << 3) + warp;

    extern __shared__ float sm[];
    float* xs = sm;
    float* ys = sm + NQ;
    float* zs = sm + 2 * NQ;
    unsigned long long* cand =
        (unsigned long long*)(sm + 3 * NQ) + (size_t)warp * CAND_CAP;

    const float* xb = xyz + (size_t)b * NQ * 3;
    for (int idx = t; idx < NQ * 3; idx += 256) {
        float v = xb[idx];
        int p = idx / 3;
        int j = idx - 3 * p;
        if (j == 0) xs[p] = v; else if (j == 1) ys[p] = v; else zs[p] = v;
    }
    __syncthreads();

    const float* cc = &new_xyz[((size_t)b * SQ + s) * 3];
    const float cx = cc[0], cy = cc[1], cz = cc[2];

    int cnt = 0;
#pragma unroll 4
    for (int j = 0; j < NQ / 32; j++) {
        int p = (j << 5) + lane;
        float dx = xs[p] - cx, dy = ys[p] - cy, dz = zs[p] - cz;
        float d = dx * dx;
        d = fmaf(dy, dy, d);
        d = fmaf(dz, dz, d);
        bool in = (d <= 0.04f);
        unsigned m = __ballot_sync(0xffffffffu, in);
        int pos = cnt + __popc(m & ((1u << lane) - 1u));
        if (in && pos < CAND_CAP)
            cand[pos] = ((unsigned long long)__float_as_uint(d) << 32) |
                        (unsigned)p;
        cnt += __popc(m);
    }
    __syncwarp();
    int L = cnt < CAND_CAP ? cnt : CAND_CAP;

    int* go = &g_group_idx[((size_t)b * SQ + s) * KQ];

    for (int c = lane; c < L; c += 32) {
        unsigned long long key = cand[c];
        int rank = 0;
        for (int j = 0; j < L; j++) rank += (cand[j] < key);
        if (rank < KQ) go[rank] = (int)(unsigned)key;
    }

    if (L < KQ) {
        int fillpos = L;
        for (int base = 0; base < NQ && fillpos < KQ; base += 32) {
            int p = base + lane;
            float dx = xs[p] - cx, dy = ys[p] - cy, dz = zs[p] - cz;
            float d = dx * dx;
            d = fmaf(dy, dy, d);
            d = fmaf(dz, dz, d);
            bool ob = (d > 0.04f);
            unsigned m = __ballot_sync(0xffffffffu, ob);
            int pos = fillpos + __popc(m & ((1u << lane) - 1u));
            if (ob && pos < KQ) go[pos] = p;
            fillpos += __popc(m);
        }
    }
}

// ---------------------------------------------------------------------------
// Kernel 3: fused MLP; conflict-free fragment-major A (1x LDS.128) +
// packed B (1x LDG.64) per (kt,·). 2 centers/block, 4 warps x 32 channels.
// ---------------------------------------------------------------------------
template<int KT>
__device__ __forceinline__ void gemm_layer(
    const unsigned* __restrict__ P, const uint2* __restrict__ Wp,
    int lane, int g, int tg, int nb, float acc[4][4][4])
{
#pragma unroll
    for (int mi = 0; mi < 4; mi++)
#pragma unroll
        for (int nt = 0; nt < 4; nt++)
#pragma unroll
            for (int q = 0; q < 4; q++) acc[mi][nt][q] = 0.f;

#pragma unroll
    for (int kt = 0; kt < KT; kt++) {
        uint4 a[4];
#pragma unroll
        for (int mi = 0; mi < 4; mi++)
            a[mi] = *(const uint4*)&P[(((kt * 4 + mi) * 32 + lane) << 2)];
#pragma unroll
        for (int nt = 0; nt < 4; nt++) {
            int nc = nb + (nt << 3) + g;
            uint2 bb = __ldg(&Wp[(kt * 128 + nc) * 4 + tg]);
#pragma unroll
            for (int mi = 0; mi < 4; mi++)
                mma_tf32(acc[mi][nt][0], acc[mi][nt][1],
                         acc[mi][nt][2], acc[mi][nt][3],
                         a[mi].x, a[mi].y, a[mi].z, a[mi].w, bb.x, bb.y);
        }
    }
}

__global__ __launch_bounds__(128) void mlp_kernel(
    const float* __restrict__ xyz, const float* __restrict__ feats,
    const float* __restrict__ new_xyz,
    const float* __restrict__ b1, const float* __restrict__ b2,
    const float* __restrict__ b3, const float* __restrict__ b4,
    float* __restrict__ f_out)
{
    const int bs0 = blockIdx.x << 1;
    const int b   = bs0 >> 10;
    const int t   = threadIdx.x;
    const int lane = t & 31;
    const int warp = t >> 5;
    const int g  = lane >> 2;
    const int tg = lane & 3;
    const int nb = warp << 5;

    extern __shared__ unsigned dynsm[];
    unsigned* P    = dynsm;                       // 17*4*32*4 = 8704 words
    float*    Fbuf = (float*)(dynsm + 8704);      // 64*FS = 8448 words
    float*    xns  = Fbuf + 64 * FS;              // 192
    float*    mb   = xns + 192;                   // 256 means
    __shared__ int   gi[2 * KQ];
    __shared__ float ctr[6];

    if (t < 2 * KQ) gi[t] = g_group_idx[(size_t)bs0 * KQ + t];
    if (t >= 64 && t < 70) ctr[t - 64] = new_xyz[(size_t)bs0 * 3 + (t - 64)];
    __syncthreads();

    // ---- gather into fragment-major P: c0-2 xn, c3-66 feats, c67-71 zero ----
    const float* fb = feats + (size_t)b * NQ * CQ;
    for (int e = t; e < 32 * CQ; e += 128) {              // row-pairs x channels
        int pr = e >> 6, ch = e & 63;
        int r = ((pr >> 3) << 4) + (pr & 7);
        float v0 = fb[(size_t)gi[r] * CQ + ch];
        float v8 = fb[(size_t)gi[r + 8] * CQ + ch];
        *(uint2*)&P[pidx(r, ch + 3)] = make_uint2(f2tf(v0), f2tf(v8));
    }
    if (t < 96) {                                          // xn
        int pr = t / 3, j = t % 3;
        int r = ((pr >> 3) << 4) + (pr & 7);
        int cen = r >> 5;
        float v0 = xyz[((size_t)b * NQ + gi[r]) * 3 + j]     - ctr[cen * 3 + j];
        float v8 = xyz[((size_t)b * NQ + gi[r + 8]) * 3 + j] - ctr[cen * 3 + j];
        xns[cen * 96 + j * 32 + (r & 31)]       = v0;
        xns[cen * 96 + j * 32 + ((r + 8) & 31)] = v8;
        *(uint2*)&P[pidx(r, j)] = make_uint2(f2tf(v0), f2tf(v8));
    }
    for (int e = t; e < 160; e += 128) {                   // zero pad c67..71
        int pr = e / 5, c = 67 + e % 5;
        int r = ((pr >> 3) << 4) + (pr & 7);
        *(uint2*)&P[pidx(r, c)] = make_uint2(0u, 0u);
    }
    __syncthreads();

    float acc[4][4][4];

    // ----- Layer 1: 72(pad) -> 128, relu -----
    gemm_layer<9>(P, g_W1p, lane, g, tg, nb, acc);
    __syncthreads();
#pragma unroll
    for (int nt = 0; nt < 4; nt++) {
        int cc = nb + (nt << 3) + 2 * tg;
        float bb0 = __ldg(&b1[cc]), bb1 = __ldg(&b1[cc + 1]);
#pragma unroll
        for (int mi = 0; mi < 4; mi++) {
            int r = mi * 16 + g;
            *(uint2*)&P[pidx(r, cc)] = make_uint2(
                f2tf(fmaxf(acc[mi][nt][0] + bb0, 0.f)),
                f2tf(fmaxf(acc[mi][nt][2] + bb0, 0.f)));
            *(uint2*)&P[pidx(r, cc + 1)] = make_uint2(
                f2tf(fmaxf(acc[mi][nt][1] + bb1, 0.f)),
                f2tf(fmaxf(acc[mi][nt][3] + bb1, 0.f)));
        }
    }
    __syncthreads();

    // ----- Layer 2: 128 -> 128, relu -> Fbuf (fp32) -----
    gemm_layer<16>(P, g_W2p, lane, g, tg, nb, acc);
#pragma unroll
    for (int nt = 0; nt < 4; nt++) {
        int cc = nb + (nt << 3) + 2 * tg;
        float bb0 = __ldg(&b2[cc]), bb1 = __ldg(&b2[cc + 1]);
#pragma unroll
        for (int mi = 0; mi < 4; mi++) {
            int r0 = mi * 16 + g;
            Fbuf[r0 * FS + cc]           = fmaxf(acc[mi][nt][0] + bb0, 0.f);
            Fbuf[r0 * FS + cc + 1]       = fmaxf(acc[mi][nt][1] + bb1, 0.f);
            Fbuf[(r0 + 8) * FS + cc]     = fmaxf(acc[mi][nt][2] + bb0, 0.f);
            Fbuf[(r0 + 8) * FS + cc + 1] = fmaxf(acc[mi][nt][3] + bb1, 0.f);
        }
    }
    __syncthreads();

    // ---- means per center/channel ----
    {
        float m0 = 0.f, m1 = 0.f;
#pragma unroll 8
        for (int r = 0; r < 32; r++) {
            m0 += Fbuf[r * FS + t];
            m1 += Fbuf[(r + 32) * FS + t];
        }
        mb[t]       = m0 * (1.f / 32.f);
        mb[128 + t] = m1 * (1.f / 32.f);
    }
    __syncthreads();

    // ---- A2 into P: c0-2 xn, c3-130 f'-mean, c131-135 zero ----
#pragma unroll
    for (int nt = 0; nt < 4; nt++) {
        int cc = nb + (nt << 3) + 2 * tg;
#pragma unroll
        for (int mi = 0; mi < 4; mi++) {
            int r = mi * 16 + g;
            int cen = mi >> 1;
            float mc0 = mb[cen * 128 + cc], mc1 = mb[cen * 128 + cc + 1];
            *(uint2*)&P[pidx(r, cc + 3)] = make_uint2(
                f2tf(Fbuf[r * FS + cc] - mc0),
                f2tf(Fbuf[(r + 8) * FS + cc] - mc0));
            *(uint2*)&P[pidx(r, cc + 4)] = make_uint2(
                f2tf(Fbuf[r * FS + cc + 1] - mc1),
                f2tf(Fbuf[(r + 8) * FS + cc + 1] - mc1));
        }
    }
    if (t < 96) {
        int pr = t / 3, j = t % 3;
        int r = ((pr >> 3) << 4) + (pr & 7);
        int cen = r >> 5;
        float v0 = xns[cen * 96 + j * 32 + (r & 31)];
        float v8 = xns[cen * 96 + j * 32 + ((r + 8) & 31)];
        *(uint2*)&P[pidx(r, j)] = make_uint2(f2tf(v0), f2tf(v8));
    }
    for (int e = t; e < 160; e += 128) {
        int pr = e / 5, c = 131 + e % 5;
        int r = ((pr >> 3) << 4) + (pr & 7);
        *(uint2*)&P[pidx(r, c)] = make_uint2(0u, 0u);
    }
    __syncthreads();

    // ----- Layer 3: 136(pad) -> 128, relu -----
    gemm_layer<17>(P, g_W3p, lane, g, tg, nb, acc);
    __syncthreads();
#pragma unroll
    for (int nt = 0; nt < 4; nt++) {
        int cc = nb + (nt << 3) + 2 * tg;
        float bb0 = __ldg(&b3[cc]), bb1 = __ldg(&b3[cc + 1]);
#pragma unroll
        for (int mi = 0; mi < 4; mi++) {
            int r = mi * 16 + g;
            *(uint2*)&P[pidx(r, cc)] = make_uint2(
                f2tf(fmaxf(acc[mi][nt][0] + bb0, 0.f)),
                f2tf(fmaxf(acc[mi][nt][2] + bb0, 0.f)));
            *(uint2*)&P[pidx(r, cc + 1)] = make_uint2(
                f2tf(fmaxf(acc[mi][nt][1] + bb1, 0.f)),
                f2tf(fmaxf(acc[mi][nt][3] + bb1, 0.f)));
        }
    }
    __syncthreads();

    // ----- Layer 4: 128 -> 128, sigmoid; weighted sum per center -----
    gemm_layer<16>(P, g_W4p, lane, g, tg, nb, acc);
#pragma unroll
    for (int nt = 0; nt < 4; nt++) {
        int cc = nb + (nt << 3) + 2 * tg;
        float bb0 = __ldg(&b4[cc]), bb1 = __ldg(&b4[cc + 1]);
        float s0[2] = {0.f, 0.f}, s1[2] = {0.f, 0.f};
#pragma unroll
        for (int mi = 0; mi < 4; mi++) {
            int c = mi >> 1;
            int r0 = mi * 16 + g;
            float a0 = 1.f / (1.f + __expf(-(acc[mi][nt][0] + bb0)));
            float a1 = 1.f / (1.f + __expf(-(acc[mi][nt][1] + bb1)));
            float a2 = 1.f / (1.f + __expf(-(acc[mi][nt][2] + bb0)));
            float a3 = 1.f / (1.f + __expf(-(acc[mi][nt][3] + bb1)));
            s0[c] = fmaf(a0, Fbuf[r0 * FS + cc], s0[c]);
            s1[c] = fmaf(a1, Fbuf[r0 * FS + cc + 1], s1[c]);
            s0[c] = fmaf(a2, Fbuf[(r0 + 8) * FS + cc], s0[c]);
            s1[c] = fmaf(a3, Fbuf[(r0 + 8) * FS + cc + 1], s1[c]);
        }
#pragma unroll
        for (int off = 4; off < 32; off <<= 1) {
            s0[0] += __shfl_xor_sync(0xffffffffu, s0[0], off);
            s1[0] += __shfl_xor_sync(0xffffffffu, s1[0], off);
            s0[1] += __shfl_xor_sync(0xffffffffu, s0[1], off);
            s1[1] += __shfl_xor_sync(0xffffffffu, s1[1], off);
        }
        if (g == 0) {
            f_out[(size_t)bs0 * HQ + cc]           = s0[0];
            f_out[(size_t)bs0 * HQ + cc + 1]       = s1[0];
            f_out[((size_t)bs0 + 1) * HQ + cc]     = s0[1];
            f_out[((size_t)bs0 + 1) * HQ + cc + 1] = s1[1];
        }
    }
}

// ---------------------------------------------------------------------------
extern "C" void kernel_launch(void* const* d_in, const int* in_sizes, int n_in,
                              void* d_out, int out_size)
{
    const float* xyz   = (const float*)d_in[0];
    const float* feats = (const float*)d_in[1];
    const float* W1 = (const float*)d_in[2];
    const float* b1 = (const float*)d_in[3];
    const float* W2 = (const float*)d_in[4];
    const float* b2 = (const float*)d_in[5];
    const float* W3 = (const float*)d_in[6];
    const float* b3 = (const float*)d_in[7];
    const float* W4 = (const float*)d_in[8];
    const float* b4 = (const float*)d_in[9];

    float* out     = (float*)d_out;
    float* new_xyz = out;
    float* f_out   = out + (size_t)BQ * SQ * 3;

    const int fps_smem  = 3 * NQ * sizeof(float);                       // 48KB
    const int ball_smem = fps_smem + 8 * CAND_CAP * sizeof(long long);  // 96KB
    const int mlp_smem  = (8704 + 64 * FS + 192 + 256) * 4;             // ~69KB
    cudaFuncSetAttribute(fps_kernel,
                         cudaFuncAttributeMaxDynamicSharedMemorySize, fps_smem);
    cudaFuncSetAttribute(ball_kernel,
                         cudaFuncAttributeMaxDynamicSharedMemorySize, ball_smem);
    cudaFuncSetAttribute(mlp_kernel,
                         cudaFuncAttributeMaxDynamicSharedMemorySize, mlp_smem);

    cvt_w_kernel<<<(17 * 512 + 255) / 256, 256>>>(W1, W2, W3, W4);
    fps_kernel <<<BQ, 512, fps_smem>>>(xyz, new_xyz);
    ball_kernel<<<(BQ * SQ) / 8, 256, ball_smem>>>(xyz, new_xyz);
    mlp_kernel <<<(BQ * SQ) / 2, 128, mlp_smem>>>(xyz, feats, new_xyz,
                                                  b1, b2, b3, b4, f_out);
}

// round 8
// speedup vs baseline: 1.2731x; 1.0303x over previous
#include <cuda_runtime.h>
#include <math.h>

#define BQ 16
#define NQ 4096
#define SQ 1024
#define KQ 32
#define CQ 64
#define HQ 128
#define CAND_CAP 768
#define FS 132        // Fbuf stride (words)

__device__ int g_group_idx[BQ * SQ * KQ];

// weights pre-packed as per-thread MMA B-fragments: uint2{b0,b1} at
// index (kt*128 + n)*4 + tg, where b0=W[kt*8+tg][n], b1=W[kt*8+4+tg][n]
__device__ uint2 g_W1p[9  * 512];
__device__ uint2 g_W2p[16 * 512];
__device__ uint2 g_W3p[17 * 512];
__device__ uint2 g_W4p[16 * 512];

__device__ __forceinline__ unsigned f2tf(float f) {
    unsigned r; asm("cvt.rna.tf32.f32 %0, %1;" : "=r"(r) : "f"(f)); return r;
}
__device__ __forceinline__ void mma_tf32(
    float& d0, float& d1, float& d2, float& d3,
    unsigned a0, unsigned a1, unsigned a2, unsigned a3,
    unsigned b0, unsigned b1)
{
    asm("mma.sync.aligned.m16n8k8.row.col.f32.tf32.tf32.f32 "
        "{%0,%1,%2,%3}, {%4,%5,%6,%7}, {%8,%9}, {%0,%1,%2,%3};"
        : "+f"(d0), "+f"(d1), "+f"(d2), "+f"(d3)
        : "r"(a0), "r"(a1), "r"(a2), "r"(a3), "r"(b0), "r"(b1));
}

// packed f32x2 (per-half IEEE fp32, bitwise identical to scalar ops)
__device__ __forceinline__ unsigned long long add2(
    unsigned long long a, unsigned long long b)
{
    unsigned long long d;
    asm("add.rn.f32x2 %0, %1, %2;" : "=l"(d) : "l"(a), "l"(b));
    return d;
}
__device__ __forceinline__ unsigned long long mul2(
    unsigned long long a, unsigned long long b)
{
    unsigned long long d;
    asm("mul.rn.f32x2 %0, %1, %2;" : "=l"(d) : "l"(a), "l"(b));
    return d;
}
__device__ __forceinline__ unsigned long long fma2(
    unsigned long long a, unsigned long long b, unsigned long long c)
{
    unsigned long long d;
    asm("fma.rn.f32x2 %0, %1, %2, %3;" : "=l"(d) : "l"(a), "l"(b), "l"(c));
    return d;
}
__device__ __forceinline__ unsigned long long bcast2(float w)
{
    unsigned long long d; unsigned u = __float_as_uint(w);
    asm("mov.b64 %0, {%1, %1};" : "=l"(d) : "r"(u));
    return d;
}
__device__ __forceinline__ float2 unpk2(unsigned long long a)
{
    float2 f;
    asm("mov.b64 {%0, %1}, %2;" : "=f"(f.x), "=f"(f.y) : "l"(a));
    return f;
}

// fragment-major A index (word): chunk = (kt*4+mi)*32 + ls, ls = OWNER LANE
// = (r&7)*4 + (c&3); reg = ((r>>3)&1) + 2*((c>>2)&1).
__device__ __forceinline__ int pidx(int r, int c) {
    int kt = c >> 3, mi = r >> 4;
    int ls = (r & 7) * 4 + (c & 3);
    int reg = ((r >> 3) & 1) + 2 * ((c >> 2) & 1);
    return (((kt * 4 + mi) * 32 + ls) << 2) + reg;
}

// ---------------------------------------------------------------------------
// Kernel 0: convert + pack weights into per-thread tf32 B-fragments.
// ---------------------------------------------------------------------------
__device__ __forceinline__ void pack_w(int i, int KT, int Kreal,
                                       const float* __restrict__ W, uint2* out)
{
    if (i < KT * 512) {
        int kt = i >> 9, rem = i & 511, n = rem >> 2, tg = rem & 3;
        int k0 = kt * 8 + tg;
        float w0 = (k0     < Kreal) ? W[k0 * 128 + n]       : 0.f;
        float w1 = (k0 + 4 < Kreal) ? W[(k0 + 4) * 128 + n] : 0.f;
        out[i] = make_uint2(f2tf(w0), f2tf(w1));
    }
}
__global__ void cvt_w_kernel(const float* __restrict__ W1,
                             const float* __restrict__ W2,
                             const float* __restrict__ W3,
                             const float* __restrict__ W4)
{
    int i = blockIdx.x * 256 + threadIdx.x;
    pack_w(i, 9,  67,  W1, g_W1p);
    pack_w(i, 16, 128, W2, g_W2p);
    pack_w(i, 17, 131, W3, g_W3p);
    pack_w(i, 16, 128, W4, g_W4p);
}

// ---------------------------------------------------------------------------
// Kernel 1: FPS. 512 threads, 8 pts/thread. Packed f32x2 distance update
// (bitwise identical to scalar), IMNMX value tree + match-mask index
// recovery, redux.sync reductions. Exact first-index argmax semantics.
// ---------------------------------------------------------------------------
__global__ __launch_bounds__(512) void fps_kernel(
    const float* __restrict__ xyz, float* __restrict__ new_xyz)
{
    const int b = blockIdx.x;
    const int t = threadIdx.x;
    const int lane = t & 31;
    const int warp = t >> 5;
    extern __shared__ float sm[];
    float* xs = sm;
    float* ys = sm + NQ;
    float* zs = sm + 2 * NQ;
    __shared__ unsigned sv[2][16];
    __shared__ int      si[2][16];

    const float* xb = xyz + (size_t)b * NQ * 3;
    for (int idx = t; idx < NQ * 3; idx += 512) {
        float v = xb[idx];
        int p = idx / 3;
        int j = idx - 3 * p;
        if (j == 0) xs[p] = v; else if (j == 1) ys[p] = v; else zs[p] = v;
    }
    __syncthreads();

    // packed coords: pair q holds points p=t+(2q)*512 (lo), p=t+(2q+1)*512 (hi)
    unsigned long long px2[4], py2[4], pz2[4];
    float dmin[8];
#pragma unroll
    for (int q = 0; q < 4; q++) {
        int p0 = t + ((2 * q) << 9), p1 = t + ((2 * q + 1) << 9);
        px2[q] = (unsigned long long)__float_as_uint(xs[p0]) |
                 ((unsigned long long)__float_as_uint(xs[p1]) << 32);
        py2[q] = (unsigned long long)__float_as_uint(ys[p0]) |
                 ((unsigned long long)__float_as_uint(ys[p1]) << 32);
        pz2[q] = (unsigned long long)__float_as_uint(zs[p0]) |
                 ((unsigned long long)__float_as_uint(zs[p1]) << 32);
        dmin[2 * q] = 3.0e38f; dmin[2 * q + 1] = 3.0e38f;
    }
    float cx = xs[0], cy = ys[0], cz = zs[0];
    if (t == 0) {
        float* o = &new_xyz[(size_t)b * SQ * 3];
        o[0] = cx; o[1] = cy; o[2] = cz;
    }

    for (int i = 1; i < SQ; i++) {
        // dist update with previous center (packed, 2 pts/op)
        unsigned long long ncx = bcast2(-cx), ncy = bcast2(-cy), ncz = bcast2(-cz);
        unsigned bb[8];
#pragma unroll
        for (int q = 0; q < 4; q++) {
            unsigned long long dx = add2(px2[q], ncx);
            unsigned long long dy = add2(py2[q], ncy);
            unsigned long long dz = add2(pz2[q], ncz);
            unsigned long long d2 = mul2(dx, dx);
            d2 = fma2(dy, dy, d2);
            d2 = fma2(dz, dz, d2);
            float2 f = unpk2(d2);
            float a = fminf(dmin[2 * q], f.x);
            float c = fminf(dmin[2 * q + 1], f.y);
            dmin[2 * q] = a; dmin[2 * q + 1] = c;
            bb[2 * q] = __float_as_uint(a);       // >=0 -> order-preserving
            bb[2 * q + 1] = __float_as_uint(c);
        }
        // value tree (7 max) -> warp max
        unsigned m01 = max(bb[0], bb[1]), m23 = max(bb[2], bb[3]);
        unsigned m45 = max(bb[4], bb[5]), m67 = max(bb[6], bb[7]);
        unsigned mloc = max(max(m01, m23), max(m45, m67));
        unsigned vmax = __reduce_max_sync(0xffffffffu, mloc);
        // match mask -> first local r -> global p; warp min-index
        unsigned mk = 0;
#pragma unroll
        for (int r = 0; r < 8; r++) mk |= (bb[r] == vmax) ? (1u << r) : 0u;
        int pl = mk ? (t + ((__ffs(mk) - 1) << 9)) : 0x7fffffff;
        int imin = __reduce_min_sync(0xffffffffu, pl);

        const int buf = i & 1;
        if (lane == 0) { sv[buf][warp] = vmax; si[buf][warp] = imin; }
        __syncthreads();
        unsigned vb = sv[buf][lane & 15];
        int      ib = si[buf][lane & 15];
        unsigned vm = __reduce_max_sync(0xffffffffu, vb);
        int c2 = (vb == vm) ? ib : 0x7fffffff;
        int im = __reduce_min_sync(0xffffffffu, c2);
        cx = xs[im]; cy = ys[im]; cz = zs[im];
        if (t == 0) {
            float* o = &new_xyz[((size_t)b * SQ + i) * 3];
            o[0] = cx; o[1] = cy; o[2] = cz;
        }
    }
}

// ---------------------------------------------------------------------------
// Kernel 2: ball query (unchanged).
// ---------------------------------------------------------------------------
__global__ __launch_bounds__(256) void ball_kernel(
    const float* __restrict__ xyz, const float* __restrict__ new_xyz)
{
    const int blk = blockIdx.x;
    const int b = blk >> 7;
    const int t = threadIdx.x;
    const int lane = t & 31;
    const int warp = t >> 5;
    const int s = ((blk & 127) << 3) + warp;

    extern __shared__ float sm[];
    float* xs = sm;
    float* ys = sm + NQ;
    float* zs = sm + 2 * NQ;
    unsigned long long* cand =
        (unsigned long long*)(sm + 3 * NQ) + (size_t)warp * CAND_CAP;

    const float* xb = xyz + (size_t)b * NQ * 3;
    for (int idx = t; idx < NQ * 3; idx += 256) {
        float v = xb[idx];
        int p = idx / 3;
        int j = idx - 3 * p;
        if (j == 0) xs[p] = v; else if (j == 1) ys[p] = v; else zs[p] = v;
    }
    __syncthreads();

    const float* cc = &new_xyz[((size_t)b * SQ + s) * 3];
    const float cx = cc[0], cy = cc[1], cz = cc[2];

    int cnt = 0;
#pragma unroll 4
    for (int j = 0; j < NQ / 32; j++) {
        int p = (j << 5) + lane;
        float dx = xs[p] - cx, dy = ys[p] - cy, dz = zs[p] - cz;
        float d = dx * dx;
        d = fmaf(dy, dy, d);
        d = fmaf(dz, dz, d);
        bool in = (d <= 0.04f);
        unsigned m = __ballot_sync(0xffffffffu, in);
        int pos = cnt + __popc(m & ((1u << lane) - 1u));
        if (in && pos < CAND_CAP)
            cand[pos] = ((unsigned long long)__float_as_uint(d) << 32) |
                        (unsigned)p;
        cnt += __popc(m);
    }
    __syncwarp();
    int L = cnt < CAND_CAP ? cnt : CAND_CAP;

    int* go = &g_group_idx[((size_t)b * SQ + s) * KQ];

    for (int c = lane; c < L; c += 32) {
        unsigned long long key = cand[c];
        int rank = 0;
        for (int j = 0; j < L; j++) rank += (cand[j] < key);
        if (rank < KQ) go[rank] = (int)(unsigned)key;
    }

    if (L < KQ) {
        int fillpos = L;
        for (int base = 0; base < NQ && fillpos < KQ; base += 32) {
            int p = base + lane;
            float dx = xs[p] - cx, dy = ys[p] - cy, dz = zs[p] - cz;
            float d = dx * dx;
            d = fmaf(dy, dy, d);
            d = fmaf(dz, dz, d);
            bool ob = (d > 0.04f);
            unsigned m = __ballot_sync(0xffffffffu, ob);
            int pos = fillpos + __popc(m & ((1u << lane) - 1u));
            if (ob && pos < KQ) go[pos] = p;
            fillpos += __popc(m);
        }
    }
}

// ---------------------------------------------------------------------------
// Kernel 3: fused MLP (unchanged from R7 — 457us, tensor 45%).
// ---------------------------------------------------------------------------
template<int KT>
__device__ __forceinline__ void gemm_layer(
    const unsigned* __restrict__ P, const uint2* __restrict__ Wp,
    int lane, int g, int tg, int nb, float acc[4][4][4])
{
#pragma unroll
    for (int mi = 0; mi < 4; mi++)
#pragma unroll
        for (int nt = 0; nt < 4; nt++)
#pragma unroll
            for (int q = 0; q < 4; q++) acc[mi][nt][q] = 0.f;

#pragma unroll
    for (int kt = 0; kt < KT; kt++) {
        uint4 a[4];
#pragma unroll
        for (int mi = 0; mi < 4; mi++)
            a[mi] = *(const uint4*)&P[(((kt * 4 + mi) * 32 + lane) << 2)];
#pragma unroll
        for (int nt = 0; nt < 4; nt++) {
            int nc = nb + (nt << 3) + g;
            uint2 bb = __ldg(&Wp[(kt * 128 + nc) * 4 + tg]);
#pragma unroll
            for (int mi = 0; mi < 4; mi++)
                mma_tf32(acc[mi][nt][0], acc[mi][nt][1],
                         acc[mi][nt][2], acc[mi][nt][3],
                         a[mi].x, a[mi].y, a[mi].z, a[mi].w, bb.x, bb.y);
        }
    }
}

__global__ __launch_bounds__(128) void mlp_kernel(
    const float* __restrict__ xyz, const float* __restrict__ feats,
    const float* __restrict__ new_xyz,
    const float* __restrict__ b1, const float* __restrict__ b2,
    const float* __restrict__ b3, const float* __restrict__ b4,
    float* __restrict__ f_out)
{
    const int bs0 = blockIdx.x << 1;
    const int b   = bs0 >> 10;
    const int t   = threadIdx.x;
    const int lane = t & 31;
    const int warp = t >> 5;
    const int g  = lane >> 2;
    const int tg = lane & 3;
    const int nb = warp << 5;

    extern __shared__ unsigned dynsm[];
    unsigned* P    = dynsm;                       // 8704 words
    float*    Fbuf = (float*)(dynsm + 8704);      // 64*FS words
    float*    xns  = Fbuf + 64 * FS;              // 192
    float*    mb   = xns + 192;                   // 256
    __shared__ int   gi[2 * KQ];
    __shared__ float ctr[6];

    if (t < 2 * KQ) gi[t] = g_group_idx[(size_t)bs0 * KQ + t];
    if (t >= 64 && t < 70) ctr[t - 64] = new_xyz[(size_t)bs0 * 3 + (t - 64)];
    __syncthreads();

    const float* fb = feats + (size_t)b * NQ * CQ;
    for (int e = t; e < 32 * CQ; e += 128) {
        int pr = e >> 6, ch = e & 63;
        int r = ((pr >> 3) << 4) + (pr & 7);
        float v0 = fb[(size_t)gi[r] * CQ + ch];
        float v8 = fb[(size_t)gi[r + 8] * CQ + ch];
        *(uint2*)&P[pidx(r, ch + 3)] = make_uint2(f2tf(v0), f2tf(v8));
    }
    if (t < 96) {
        int pr = t / 3, j = t % 3;
        int r = ((pr >> 3) << 4) + (pr & 7);
        int cen = r >> 5;
        float v0 = xyz[((size_t)b * NQ + gi[r]) * 3 + j]     - ctr[cen * 3 + j];
        float v8 = xyz[((size_t)b * NQ + gi[r + 8]) * 3 + j] - ctr[cen * 3 + j];
        xns[cen * 96 + j * 32 + (r & 31)]       = v0;
        xns[cen * 96 + j * 32 + ((r + 8) & 31)] = v8;
        *(uint2*)&P[pidx(r, j)] = make_uint2(f2tf(v0), f2tf(v8));
    }
    for (int e = t; e < 160; e += 128) {
        int pr = e / 5, c = 67 + e % 5;
        int r = ((pr >> 3) << 4) + (pr & 7);
        *(uint2*)&P[pidx(r, c)] = make_uint2(0u, 0u);
    }
    __syncthreads();

    float acc[4][4][4];

    gemm_layer<9>(P, g_W1p, lane, g, tg, nb, acc);
    __syncthreads();
#pragma unroll
    for (int nt = 0; nt < 4; nt++) {
        int cc = nb + (nt << 3) + 2 * tg;
        float bb0 = __ldg(&b1[cc]), bb1 = __ldg(&b1[cc + 1]);
#pragma unroll
        for (int mi = 0; mi < 4; mi++) {
            int r = mi * 16 + g;
            *(uint2*)&P[pidx(r, cc)] = make_uint2(
                f2tf(fmaxf(acc[mi][nt][0] + bb0, 0.f)),
                f2tf(fmaxf(acc[mi][nt][2] + bb0, 0.f)));
            *(uint2*)&P[pidx(r, cc + 1)] = make_uint2(
                f2tf(fmaxf(acc[mi][nt][1] + bb1, 0.f)),
                f2tf(fmaxf(acc[mi][nt][3] + bb1, 0.f)));
        }
    }
    __syncthreads();

    gemm_layer<16>(P, g_W2p, lane, g, tg, nb, acc);
#pragma unroll
    for (int nt = 0; nt < 4; nt++) {
        int cc = nb + (nt << 3) + 2 * tg;
        float bb0 = __ldg(&b2[cc]), bb1 = __ldg(&b2[cc + 1]);
#pragma unroll
        for (int mi = 0; mi < 4; mi++) {
            int r0 = mi * 16 + g;
            Fbuf[r0 * FS + cc]           = fmaxf(acc[mi][nt][0] + bb0, 0.f);
            Fbuf[r0 * FS + cc + 1]       = fmaxf(acc[mi][nt][1] + bb1, 0.f);
            Fbuf[(r0 + 8) * FS + cc]     = fmaxf(acc[mi][nt][2] + bb0, 0.f);
            Fbuf[(r0 + 8) * FS + cc + 1] = fmaxf(acc[mi][nt][3] + bb1, 0.f);
        }
    }
    __syncthreads();

    {
        float m0 = 0.f, m1 = 0.f;
#pragma unroll 8
        for (int r = 0; r < 32; r++) {
            m0 += Fbuf[r * FS + t];
            m1 += Fbuf[(r + 32) * FS + t];
        }
        mb[t]       = m0 * (1.f / 32.f);
        mb[128 + t] = m1 * (1.f / 32.f);
    }
    __syncthreads();

#pragma unroll
    for (int nt = 0; nt < 4; nt++) {
        int cc = nb + (nt << 3) + 2 * tg;
#pragma unroll
        for (int mi = 0; mi < 4; mi++) {
            int r = mi * 16 + g;
            int cen = mi >> 1;
            float mc0 = mb[cen * 128 + cc], mc1 = mb[cen * 128 + cc + 1];
            *(uint2*)&P[pidx(r, cc + 3)] = make_uint2(
                f2tf(Fbuf[r * FS + cc] - mc0),
                f2tf(Fbuf[(r + 8) * FS + cc] - mc0));
            *(uint2*)&P[pidx(r, cc + 4)] = make_uint2(
                f2tf(Fbuf[r * FS + cc + 1] - mc1),
                f2tf(Fbuf[(r + 8) * FS + cc + 1] - mc1));
        }
    }
    if (t < 96) {
        int pr = t / 3, j = t % 3;
        int r = ((pr >> 3) << 4) + (pr & 7);
        int cen = r >> 5;
        float v0 = xns[cen * 96 + j * 32 + (r & 31)];
        float v8 = xns[cen * 96 + j * 32 + ((r + 8) & 31)];
        *(uint2*)&P[pidx(r, j)] = make_uint2(f2tf(v0), f2tf(v8));
    }
    for (int e = t; e < 160; e += 128) {
        int pr = e / 5, c = 131 + e % 5;
        int r = ((pr >> 3) << 4) + (pr & 7);
        *(uint2*)&P[pidx(r, c)] = make_uint2(0u, 0u);
    }
    __syncthreads();

    gemm_layer<17>(P, g_W3p, lane, g, tg, nb, acc);
    __syncthreads();
#pragma unroll
    for (int nt = 0; nt < 4; nt++) {
        int cc = nb + (nt << 3) + 2 * tg;
        float bb0 = __ldg(&b3[cc]), bb1 = __ldg(&b3[cc + 1]);
#pragma unroll
        for (int mi = 0; mi < 4; mi++) {
            int r = mi * 16 + g;
            *(uint2*)&P[pidx(r, cc)] = make_uint2(
                f2tf(fmaxf(acc[mi][nt][0] + bb0, 0.f)),
                f2tf(fmaxf(acc[mi][nt][2] + bb0, 0.f)));
            *(uint2*)&P[pidx(r, cc + 1)] = make_uint2(
                f2tf(fmaxf(acc[mi][nt][1] + bb1, 0.f)),
                f2tf(fmaxf(acc[mi][nt][3] + bb1, 0.f)));
        }
    }
    __syncthreads();

    gemm_layer<16>(P, g_W4p, lane, g, tg, nb, acc);
#pragma unroll
    for (int nt = 0; nt < 4; nt++) {
        int cc = nb + (nt << 3) + 2 * tg;
        float bb0 = __ldg(&b4[cc]), bb1 = __ldg(&b4[cc + 1]);
        float s0[2] = {0.f, 0.f}, s1[2] = {0.f, 0.f};
#pragma unroll
        for (int mi = 0; mi < 4; mi++) {
            int c = mi >> 1;
            int r0 = mi * 16 + g;
            float a0 = 1.f / (1.f + __expf(-(acc[mi][nt][0] + bb0)));
            float a1 = 1.f / (1.f + __expf(-(acc[mi][nt][1] + bb1)));
            float a2 = 1.f / (1.f + __expf(-(acc[mi][nt][2] + bb0)));
            float a3 = 1.f / (1.f + __expf(-(acc[mi][nt][3] + bb1)));
            s0[c] = fmaf(a0, Fbuf[r0 * FS + cc], s0[c]);
            s1[c] = fmaf(a1, Fbuf[r0 * FS + cc + 1], s1[c]);
            s0[c] = fmaf(a2, Fbuf[(r0 + 8) * FS + cc], s0[c]);
            s1[c] = fmaf(a3, Fbuf[(r0 + 8) * FS + cc + 1], s1[c]);
        }
#pragma unroll
        for (int off = 4; off < 32; off <<= 1) {
            s0[0] += __shfl_xor_sync(0xffffffffu, s0[0], off);
            s1[0] += __shfl_xor_sync(0xffffffffu, s1[0], off);
            s0[1] += __shfl_xor_sync(0xffffffffu, s0[1], off);
            s1[1] += __shfl_xor_sync(0xffffffffu, s1[1], off);
        }
        if (g == 0) {
            f_out[(size_t)bs0 * HQ + cc]           = s0[0];
            f_out[(size_t)bs0 * HQ + cc + 1]       = s1[0];
            f_out[((size_t)bs0 + 1) * HQ + cc]     = s0[1];
            f_out[((size_t)bs0 + 1) * HQ + cc + 1] = s1[1];
        }
    }
}

// ---------------------------------------------------------------------------
extern "C" void kernel_launch(void* const* d_in, const int* in_sizes, int n_in,
                              void* d_out, int out_size)
{
    const float* xyz   = (const float*)d_in[0];
    const float* feats = (const float*)d_in[1];
    const float* W1 = (const float*)d_in[2];
    const float* b1 = (const float*)d_in[3];
    const float* W2 = (const float*)d_in[4];
    const float* b2 = (const float*)d_in[5];
    const float* W3 = (const float*)d_in[6];
    const float* b3 = (const float*)d_in[7];
    const float* W4 = (const float*)d_in[8];
    const float* b4 = (const float*)d_in[9];

    float* out     = (float*)d_out;
    float* new_xyz = out;
    float* f_out   = out + (size_t)BQ * SQ * 3;

    const int fps_smem  = 3 * NQ * sizeof(float);                       // 48KB
    const int ball_smem = fps_smem + 8 * CAND_CAP * sizeof(long long);  // 96KB
    const int mlp_smem  = (8704 + 64 * FS + 192 + 256) * 4;             // ~69KB
    cudaFuncSetAttribute(fps_kernel,
                         cudaFuncAttributeMaxDynamicSharedMemorySize, fps_smem);
    cudaFuncSetAttribute(ball_kernel,
                         cudaFuncAttributeMaxDynamicSharedMemorySize, ball_smem);
    cudaFuncSetAttribute(mlp_kernel,
                         cudaFuncAttributeMaxDynamicSharedMemorySize, mlp_smem);

    cvt_w_kernel<<<(17 * 512 + 255) / 256, 256>>>(W1, W2, W3, W4);
    fps_kernel <<<BQ, 512, fps_smem>>>(xyz, new_xyz);
    ball_kernel<<<(BQ * SQ) / 8, 256, ball_smem>>>(xyz, new_xyz);
    mlp_kernel <<<(BQ * SQ) / 2, 128, mlp_smem>>>(xyz, feats, new_xyz,
                                                  b1, b2, b3, b4, f_out);
}

// round 9
// speedup vs baseline: 1.2860x; 1.0101x over previous
#include <cuda_runtime.h>
#include <math.h>

#define BQ 16
#define NQ 4096
#define SQ 1024
#define KQ 32
#define CQ 64
#define HQ 128
#define CAND_CAP 768
#define FS 132        // Fbuf stride (words)

__device__ int g_group_idx[BQ * SQ * KQ];

// weights pre-packed as per-thread MMA B-fragments: uint2{b0,b1} at
// index (kt*128 + n)*4 + tg, where b0=W[kt*8+tg][n], b1=W[kt*8+4+tg][n]
__device__ uint2 g_W1p[9  * 512];
__device__ uint2 g_W2p[16 * 512];
__device__ uint2 g_W3p[17 * 512];
__device__ uint2 g_W4p[16 * 512];

__device__ __forceinline__ unsigned f2tf(float f) {
    unsigned r; asm("cvt.rna.tf32.f32 %0, %1;" : "=r"(r) : "f"(f)); return r;
}
__device__ __forceinline__ void mma_tf32(
    float& d0, float& d1, float& d2, float& d3,
    unsigned a0, unsigned a1, unsigned a2, unsigned a3,
    unsigned b0, unsigned b1)
{
    asm("mma.sync.aligned.m16n8k8.row.col.f32.tf32.tf32.f32 "
        "{%0,%1,%2,%3}, {%4,%5,%6,%7}, {%8,%9}, {%0,%1,%2,%3};"
        : "+f"(d0), "+f"(d1), "+f"(d2), "+f"(d3)
        : "r"(a0), "r"(a1), "r"(a2), "r"(a3), "r"(b0), "r"(b1));
}

// packed f32x2 (per-half IEEE fp32, bitwise identical to scalar ops)
__device__ __forceinline__ unsigned long long add2(
    unsigned long long a, unsigned long long b)
{
    unsigned long long d;
    asm("add.rn.f32x2 %0, %1, %2;" : "=l"(d) : "l"(a), "l"(b));
    return d;
}
__device__ __forceinline__ unsigned long long mul2(
    unsigned long long a, unsigned long long b)
{
    unsigned long long d;
    asm("mul.rn.f32x2 %0, %1, %2;" : "=l"(d) : "l"(a), "l"(b));
    return d;
}
__device__ __forceinline__ unsigned long long fma2(
    unsigned long long a, unsigned long long b, unsigned long long c)
{
    unsigned long long d;
    asm("fma.rn.f32x2 %0, %1, %2, %3;" : "=l"(d) : "l"(a), "l"(b), "l"(c));
    return d;
}
__device__ __forceinline__ unsigned long long bcast2(float w)
{
    unsigned long long d; unsigned u = __float_as_uint(w);
    asm("mov.b64 %0, {%1, %1};" : "=l"(d) : "r"(u));
    return d;
}
__device__ __forceinline__ float2 unpk2(unsigned long long a)
{
    float2 f;
    asm("mov.b64 {%0, %1}, %2;" : "=f"(f.x), "=f"(f.y) : "l"(a));
    return f;
}

// fragment-major A index (word): chunk = (kt*4+mi)*32 + ls, ls = OWNER LANE
// = (r&7)*4 + (c&3); reg = ((r>>3)&1) + 2*((c>>2)&1).
__device__ __forceinline__ int pidx(int r, int c) {
    int kt = c >> 3, mi = r >> 4;
    int ls = (r & 7) * 4 + (c & 3);
    int reg = ((r >> 3) & 1) + 2 * ((c >> 2) & 1);
    return (((kt * 4 + mi) * 32 + ls) << 2) + reg;
}

// ---------------------------------------------------------------------------
// Kernel 0: convert + pack weights into per-thread tf32 B-fragments.
// ---------------------------------------------------------------------------
__device__ __forceinline__ void pack_w(int i, int KT, int Kreal,
                                       const float* __restrict__ W, uint2* out)
{
    if (i < KT * 512) {
        int kt = i >> 9, rem = i & 511, n = rem >> 2, tg = rem & 3;
        int k0 = kt * 8 + tg;
        float w0 = (k0     < Kreal) ? W[k0 * 128 + n]       : 0.f;
        float w1 = (k0 + 4 < Kreal) ? W[(k0 + 4) * 128 + n] : 0.f;
        out[i] = make_uint2(f2tf(w0), f2tf(w1));
    }
}
__global__ void cvt_w_kernel(const float* __restrict__ W1,
                             const float* __restrict__ W2,
                             const float* __restrict__ W3,
                             const float* __restrict__ W4)
{
    int i = blockIdx.x * 256 + threadIdx.x;
    pack_w(i, 9,  67,  W1, g_W1p);
    pack_w(i, 16, 128, W2, g_W2p);
    pack_w(i, 17, 131, W3, g_W3p);
    pack_w(i, 16, 128, W4, g_W4p);
}

// ---------------------------------------------------------------------------
// Kernel 1: FPS (unchanged — math must stay bit-identical).
// ---------------------------------------------------------------------------
__global__ __launch_bounds__(512) void fps_kernel(
    const float* __restrict__ xyz, float* __restrict__ new_xyz)
{
    const int b = blockIdx.x;
    const int t = threadIdx.x;
    const int lane = t & 31;
    const int warp = t >> 5;
    extern __shared__ float sm[];
    float* xs = sm;
    float* ys = sm + NQ;
    float* zs = sm + 2 * NQ;
    __shared__ unsigned sv[2][16];
    __shared__ int      si[2][16];

    const float* xb = xyz + (size_t)b * NQ * 3;
    for (int idx = t; idx < NQ * 3; idx += 512) {
        float v = xb[idx];
        int p = idx / 3;
        int j = idx - 3 * p;
        if (j == 0) xs[p] = v; else if (j == 1) ys[p] = v; else zs[p] = v;
    }
    __syncthreads();

    unsigned long long px2[4], py2[4], pz2[4];
    float dmin[8];
#pragma unroll
    for (int q = 0; q < 4; q++) {
        int p0 = t + ((2 * q) << 9), p1 = t + ((2 * q + 1) << 9);
        px2[q] = (unsigned long long)__float_as_uint(xs[p0]) |
                 ((unsigned long long)__float_as_uint(xs[p1]) << 32);
        py2[q] = (unsigned long long)__float_as_uint(ys[p0]) |
                 ((unsigned long long)__float_as_uint(ys[p1]) << 32);
        pz2[q] = (unsigned long long)__float_as_uint(zs[p0]) |
                 ((unsigned long long)__float_as_uint(zs[p1]) << 32);
        dmin[2 * q] = 3.0e38f; dmin[2 * q + 1] = 3.0e38f;
    }
    float cx = xs[0], cy = ys[0], cz = zs[0];
    if (t == 0) {
        float* o = &new_xyz[(size_t)b * SQ * 3];
        o[0] = cx; o[1] = cy; o[2] = cz;
    }

    for (int i = 1; i < SQ; i++) {
        unsigned long long ncx = bcast2(-cx), ncy = bcast2(-cy), ncz = bcast2(-cz);
        unsigned bb[8];
#pragma unroll
        for (int q = 0; q < 4; q++) {
            unsigned long long dx = add2(px2[q], ncx);
            unsigned long long dy = add2(py2[q], ncy);
            unsigned long long dz = add2(pz2[q], ncz);
            unsigned long long d2 = mul2(dx, dx);
            d2 = fma2(dy, dy, d2);
            d2 = fma2(dz, dz, d2);
            float2 f = unpk2(d2);
            float a = fminf(dmin[2 * q], f.x);
            float c = fminf(dmin[2 * q + 1], f.y);
            dmin[2 * q] = a; dmin[2 * q + 1] = c;
            bb[2 * q] = __float_as_uint(a);
            bb[2 * q + 1] = __float_as_uint(c);
        }
        unsigned m01 = max(bb[0], bb[1]), m23 = max(bb[2], bb[3]);
        unsigned m45 = max(bb[4], bb[5]), m67 = max(bb[6], bb[7]);
        unsigned mloc = max(max(m01, m23), max(m45, m67));
        unsigned vmax = __reduce_max_sync(0xffffffffu, mloc);
        unsigned mk = 0;
#pragma unroll
        for (int r = 0; r < 8; r++) mk |= (bb[r] == vmax) ? (1u << r) : 0u;
        int pl = mk ? (t + ((__ffs(mk) - 1) << 9)) : 0x7fffffff;
        int imin = __reduce_min_sync(0xffffffffu, pl);

        const int buf = i & 1;
        if (lane == 0) { sv[buf][warp] = vmax; si[buf][warp] = imin; }
        __syncthreads();
        unsigned vb = sv[buf][lane & 15];
        int      ib = si[buf][lane & 15];
        unsigned vm = __reduce_max_sync(0xffffffffu, vb);
        int c2 = (vb == vm) ? ib : 0x7fffffff;
        int im = __reduce_min_sync(0xffffffffu, c2);
        cx = xs[im]; cy = ys[im]; cz = zs[im];
        if (t == 0) {
            float* o = &new_xyz[((size_t)b * SQ + i) * 3];
            o[0] = cx; o[1] = cy; o[2] = cz;
        }
    }
}

// ---------------------------------------------------------------------------
// Kernel 2: ball query (unchanged).
// ---------------------------------------------------------------------------
__global__ __launch_bounds__(256) void ball_kernel(
    const float* __restrict__ xyz, const float* __restrict__ new_xyz)
{
    const int blk = blockIdx.x;
    const int b = blk >> 7;
    const int t = threadIdx.x;
    const int lane = t & 31;
    const int warp = t >> 5;
    const int s = ((blk & 127) << 3) + warp;

    extern __shared__ float sm[];
    float* xs = sm;
    float* ys = sm + NQ;
    float* zs = sm + 2 * NQ;
    unsigned long long* cand =
        (unsigned long long*)(sm + 3 * NQ) + (size_t)warp * CAND_CAP;

    const float* xb = xyz + (size_t)b * NQ * 3;
    for (int idx = t; idx < NQ * 3; idx += 256) {
        float v = xb[idx];
        int p = idx / 3;
        int j = idx - 3 * p;
        if (j == 0) xs[p] = v; else if (j == 1) ys[p] = v; else zs[p] = v;
    }
    __syncthreads();

    const float* cc = &new_xyz[((size_t)b * SQ + s) * 3];
    const float cx = cc[0], cy = cc[1], cz = cc[2];

    int cnt = 0;
#pragma unroll 4
    for (int j = 0; j < NQ / 32; j++) {
        int p = (j << 5) + lane;
        float dx = xs[p] - cx, dy = ys[p] - cy, dz = zs[p] - cz;
        float d = dx * dx;
        d = fmaf(dy, dy, d);
        d = fmaf(dz, dz, d);
        bool in = (d <= 0.04f);
        unsigned m = __ballot_sync(0xffffffffu, in);
        int pos = cnt + __popc(m & ((1u << lane) - 1u));
        if (in && pos < CAND_CAP)
            cand[pos] = ((unsigned long long)__float_as_uint(d) << 32) |
                        (unsigned)p;
        cnt += __popc(m);
    }
    __syncwarp();
    int L = cnt < CAND_CAP ? cnt : CAND_CAP;

    int* go = &g_group_idx[((size_t)b * SQ + s) * KQ];

    for (int c = lane; c < L; c += 32) {
        unsigned long long key = cand[c];
        int rank = 0;
        for (int j = 0; j < L; j++) rank += (cand[j] < key);
        if (rank < KQ) go[rank] = (int)(unsigned)key;
    }

    if (L < KQ) {
        int fillpos = L;
        for (int base = 0; base < NQ && fillpos < KQ; base += 32) {
            int p = base + lane;
            float dx = xs[p] - cx, dy = ys[p] - cy, dz = zs[p] - cz;
            float d = dx * dx;
            d = fmaf(dy, dy, d);
            d = fmaf(dz, dz, d);
            bool ob = (d > 0.04f);
            unsigned m = __ballot_sync(0xffffffffu, ob);
            int pos = fillpos + __popc(m & ((1u << lane) - 1u));
            if (ob && pos < KQ) go[pos] = p;
            fillpos += __popc(m);
        }
    }
}

// ---------------------------------------------------------------------------
// Kernel 3: fused MLP; 256 threads, 8 warps = (wm: m-half) x (wn: 32 ch).
// Same arithmetic / register mapping as R8 -> bitwise identical output.
// 24 warps/SM (3 blocks) to feed the HMMA pipe.
// ---------------------------------------------------------------------------
template<int KT>
__device__ __forceinline__ void gemm_layer(
    const unsigned* __restrict__ P, const uint2* __restrict__ Wp,
    int lane, int g, int tg, int nb, int mibase, float acc[2][4][4])
{
#pragma unroll
    for (int mi = 0; mi < 2; mi++)
#pragma unroll
        for (int nt = 0; nt < 4; nt++)
#pragma unroll
            for (int q = 0; q < 4; q++) acc[mi][nt][q] = 0.f;

#pragma unroll
    for (int kt = 0; kt < KT; kt++) {
        uint4 a[2];
#pragma unroll
        for (int mi = 0; mi < 2; mi++)
            a[mi] = *(const uint4*)&P[(((kt * 4 + mibase + mi) * 32 + lane) << 2)];
#pragma unroll
        for (int nt = 0; nt < 4; nt++) {
            int nc = nb + (nt << 3) + g;
            uint2 bb = __ldg(&Wp[(kt * 128 + nc) * 4 + tg]);
#pragma unroll
            for (int mi = 0; mi < 2; mi++)
                mma_tf32(acc[mi][nt][0], acc[mi][nt][1],
                         acc[mi][nt][2], acc[mi][nt][3],
                         a[mi].x, a[mi].y, a[mi].z, a[mi].w, bb.x, bb.y);
        }
    }
}

__global__ __launch_bounds__(256, 3) void mlp_kernel(
    const float* __restrict__ xyz, const float* __restrict__ feats,
    const float* __restrict__ new_xyz,
    const float* __restrict__ b1, const float* __restrict__ b2,
    const float* __restrict__ b3, const float* __restrict__ b4,
    float* __restrict__ f_out)
{
    const int bs0 = blockIdx.x << 1;
    const int b   = bs0 >> 10;
    const int t   = threadIdx.x;
    const int lane = t & 31;
    const int warp = t >> 5;
    const int wm  = warp >> 2;          // m-half (== center index)
    const int wn  = warp & 3;           // channel slice
    const int g  = lane >> 2;
    const int tg = lane & 3;
    const int nb = wn << 5;
    const int mibase = wm << 1;

    extern __shared__ unsigned dynsm[];
    unsigned* P    = dynsm;                       // 8704 words
    float*    Fbuf = (float*)(dynsm + 8704);      // 64*FS words
    float*    xns  = Fbuf + 64 * FS;              // 192
    float*    mb   = xns + 192;                   // 256
    __shared__ int   gi[2 * KQ];
    __shared__ float ctr[6];

    if (t < 2 * KQ) gi[t] = g_group_idx[(size_t)bs0 * KQ + t];
    if (t >= 64 && t < 70) ctr[t - 64] = new_xyz[(size_t)bs0 * 3 + (t - 64)];
    __syncthreads();

    const float* fb = feats + (size_t)b * NQ * CQ;
    for (int e = t; e < 32 * CQ; e += 256) {
        int pr = e >> 6, ch = e & 63;
        int r = ((pr >> 3) << 4) + (pr & 7);
        float v0 = fb[(size_t)gi[r] * CQ + ch];
        float v8 = fb[(size_t)gi[r + 8] * CQ + ch];
        *(uint2*)&P[pidx(r, ch + 3)] = make_uint2(f2tf(v0), f2tf(v8));
    }
    if (t < 96) {
        int pr = t / 3, j = t % 3;
        int r = ((pr >> 3) << 4) + (pr & 7);
        int cen = r >> 5;
        float v0 = xyz[((size_t)b * NQ + gi[r]) * 3 + j]     - ctr[cen * 3 + j];
        float v8 = xyz[((size_t)b * NQ + gi[r + 8]) * 3 + j] - ctr[cen * 3 + j];
        xns[cen * 96 + j * 32 + (r & 31)]       = v0;
        xns[cen * 96 + j * 32 + ((r + 8) & 31)] = v8;
        *(uint2*)&P[pidx(r, j)] = make_uint2(f2tf(v0), f2tf(v8));
    }
    if (t < 160) {
        int pr = t / 5, c = 67 + t % 5;
        int r = ((pr >> 3) << 4) + (pr & 7);
        *(uint2*)&P[pidx(r, c)] = make_uint2(0u, 0u);
    }
    __syncthreads();

    float acc[2][4][4];

    // ----- Layer 1: 72(pad) -> 128, relu -----
    gemm_layer<9>(P, g_W1p, lane, g, tg, nb, mibase, acc);
    __syncthreads();
#pragma unroll
    for (int nt = 0; nt < 4; nt++) {
        int cc = nb + (nt << 3) + 2 * tg;
        float bb0 = __ldg(&b1[cc]), bb1 = __ldg(&b1[cc + 1]);
#pragma unroll
        for (int mi = 0; mi < 2; mi++) {
            int r = (mibase + mi) * 16 + g;
            *(uint2*)&P[pidx(r, cc)] = make_uint2(
                f2tf(fmaxf(acc[mi][nt][0] + bb0, 0.f)),
                f2tf(fmaxf(acc[mi][nt][2] + bb0, 0.f)));
            *(uint2*)&P[pidx(r, cc + 1)] = make_uint2(
                f2tf(fmaxf(acc[mi][nt][1] + bb1, 0.f)),
                f2tf(fmaxf(acc[mi][nt][3] + bb1, 0.f)));
        }
    }
    __syncthreads();

    // ----- Layer 2: 128 -> 128, relu -> Fbuf (fp32) -----
    gemm_layer<16>(P, g_W2p, lane, g, tg, nb, mibase, acc);
#pragma unroll
    for (int nt = 0; nt < 4; nt++) {
        int cc = nb + (nt << 3) + 2 * tg;
        float bb0 = __ldg(&b2[cc]), bb1 = __ldg(&b2[cc + 1]);
#pragma unroll
        for (int mi = 0; mi < 2; mi++) {
            int r0 = (mibase + mi) * 16 + g;
            Fbuf[r0 * FS + cc]           = fmaxf(acc[mi][nt][0] + bb0, 0.f);
            Fbuf[r0 * FS + cc + 1]       = fmaxf(acc[mi][nt][1] + bb1, 0.f);
            Fbuf[(r0 + 8) * FS + cc]     = fmaxf(acc[mi][nt][2] + bb0, 0.f);
            Fbuf[(r0 + 8) * FS + cc + 1] = fmaxf(acc[mi][nt][3] + bb1, 0.f);
        }
    }
    __syncthreads();

    // ---- means per center/channel (t<128: center0 ch t; t>=128: center1) ----
    {
        int cen = t >> 7, ch = t & 127;
        float m = 0.f;
#pragma unroll 8
        for (int r = 0; r < 32; r++) m += Fbuf[(cen * 32 + r) * FS + ch];
        mb[cen * 128 + ch] = m * (1.f / 32.f);
    }
    __syncthreads();

    // ---- A2 into P: c0-2 xn, c3-130 f'-mean, c131-135 zero ----
#pragma unroll
    for (int nt = 0; nt < 4; nt++) {
        int cc = nb + (nt << 3) + 2 * tg;
        float mc0 = mb[wm * 128 + cc], mc1 = mb[wm * 128 + cc + 1];
#pragma unroll
        for (int mi = 0; mi < 2; mi++) {
            int r = (mibase + mi) * 16 + g;
            *(uint2*)&P[pidx(r, cc + 3)] = make_uint2(
                f2tf(Fbuf[r * FS + cc] - mc0),
                f2tf(Fbuf[(r + 8) * FS + cc] - mc0));
            *(uint2*)&P[pidx(r, cc + 4)] = make_uint2(
                f2tf(Fbuf[r * FS + cc + 1] - mc1),
                f2tf(Fbuf[(r + 8) * FS + cc + 1] - mc1));
        }
    }
    if (t < 96) {
        int pr = t / 3, j = t % 3;
        int r = ((pr >> 3) << 4) + (pr & 7);
        int cen = r >> 5;
        float v0 = xns[cen * 96 + j * 32 + (r & 31)];
        float v8 = xns[cen * 96 + j * 32 + ((r + 8) & 31)];
        *(uint2*)&P[pidx(r, j)] = make_uint2(f2tf(v0), f2tf(v8));
    }
    if (t < 160) {
        int pr = t / 5, c = 131 + t % 5;
        int r = ((pr >> 3) << 4) + (pr & 7);
        *(uint2*)&P[pidx(r, c)] = make_uint2(0u, 0u);
    }
    __syncthreads();

    // ----- Layer 3: 136(pad) -> 128, relu -----
    gemm_layer<17>(P, g_W3p, lane, g, tg, nb, mibase, acc);
    __syncthreads();
#pragma unroll
    for (int nt = 0; nt < 4; nt++) {
        int cc = nb + (nt << 3) + 2 * tg;
        float bb0 = __ldg(&b3[cc]), bb1 = __ldg(&b3[cc + 1]);
#pragma unroll
        for (int mi = 0; mi < 2; mi++) {
            int r = (mibase + mi) * 16 + g;
            *(uint2*)&P[pidx(r, cc)] = make_uint2(
                f2tf(fmaxf(acc[mi][nt][0] + bb0, 0.f)),
                f2tf(fmaxf(acc[mi][nt][2] + bb0, 0.f)));
            *(uint2*)&P[pidx(r, cc + 1)] = make_uint2(
                f2tf(fmaxf(acc[mi][nt][1] + bb1, 0.f)),
                f2tf(fmaxf(acc[mi][nt][3] + bb1, 0.f)));
        }
    }
    __syncthreads();

    // ----- Layer 4: 128 -> 128, sigmoid; weighted sum (center = wm) -----
    gemm_layer<16>(P, g_W4p, lane, g, tg, nb, mibase, acc);
#pragma unroll
    for (int nt = 0; nt < 4; nt++) {
        int cc = nb + (nt << 3) + 2 * tg;
        float bb0 = __ldg(&b4[cc]), bb1 = __ldg(&b4[cc + 1]);
        float s0 = 0.f, s1 = 0.f;
#pragma unroll
        for (int mi = 0; mi < 2; mi++) {
            int r0 = (mibase + mi) * 16 + g;
            float a0 = 1.f / (1.f + __expf(-(acc[mi][nt][0] + bb0)));
            float a1 = 1.f / (1.f + __expf(-(acc[mi][nt][1] + bb1)));
            float a2 = 1.f / (1.f + __expf(-(acc[mi][nt][2] + bb0)));
            float a3 = 1.f / (1.f + __expf(-(acc[mi][nt][3] + bb1)));
            s0 = fmaf(a0, Fbuf[r0 * FS + cc], s0);
            s1 = fmaf(a1, Fbuf[r0 * FS + cc + 1], s1);
            s0 = fmaf(a2, Fbuf[(r0 + 8) * FS + cc], s0);
            s1 = fmaf(a3, Fbuf[(r0 + 8) * FS + cc + 1], s1);
        }
#pragma unroll
        for (int off = 4; off < 32; off <<= 1) {
            s0 += __shfl_xor_sync(0xffffffffu, s0, off);
            s1 += __shfl_xor_sync(0xffffffffu, s1, off);
        }
        if (g == 0) {
            f_out[((size_t)bs0 + wm) * HQ + cc]     = s0;
            f_out[((size_t)bs0 + wm) * HQ + cc + 1] = s1;
        }
    }
}

// ---------------------------------------------------------------------------
extern "C" void kernel_launch(void* const* d_in, const int* in_sizes, int n_in,
                              void* d_out, int out_size)
{
    const float* xyz   = (const float*)d_in[0];
    const float* feats = (const float*)d_in[1];
    const float* W1 = (const float*)d_in[2];
    const float* b1 = (const float*)d_in[3];
    const float* W2 = (const float*)d_in[4];
    const float* b2 = (const float*)d_in[5];
    const float* W3 = (const float*)d_in[6];
    const float* b3 = (const float*)d_in[7];
    const float* W4 = (const float*)d_in[8];
    const float* b4 = (const float*)d_in[9];

    float* out     = (float*)d_out;
    float* new_xyz = out;
    float* f_out   = out + (size_t)BQ * SQ * 3;

    const int fps_smem  = 3 * NQ * sizeof(float);                       // 48KB
    const int ball_smem = fps_smem + 8 * CAND_CAP * sizeof(long long);  // 96KB
    const int mlp_smem  = (8704 + 64 * FS + 192 + 256) * 4;             // ~69KB
    cudaFuncSetAttribute(fps_kernel,
                         cudaFuncAttributeMaxDynamicSharedMemorySize, fps_smem);
    cudaFuncSetAttribute(ball_kernel,
                         cudaFuncAttributeMaxDynamicSharedMemorySize, ball_smem);
    cudaFuncSetAttribute(mlp_kernel,
                         cudaFuncAttributeMaxDynamicSharedMemorySize, mlp_smem);

    cvt_w_kernel<<<(17 * 512 + 255) / 256, 256>>>(W1, W2, W3, W4);
    fps_kernel <<<BQ, 512, fps_smem>>>(xyz, new_xyz);
    ball_kernel<<<(BQ * SQ) / 8, 256, ball_smem>>>(xyz, new_xyz);
    mlp_kernel <<<(BQ * SQ) / 2, 256, mlp_smem>>>(xyz, feats, new_xyz,
                                                  b1, b2, b3, b4, f_out);
}

// round 11
// speedup vs baseline: 1.4719x; 1.1446x over previous
#include <cuda_runtime.h>
#include <cuda_fp16.h>
#include <math.h>

#define BQ 16
#define NQ 4096
#define SQ 1024
#define KQ 32
#define CQ 64
#define HQ 128
#define CAND_CAP 768
#define FS 132        // Fbuf stride (words)
#define PWORDS 4608   // 9kt * 4mi * 32 lanes * 4 words

__device__ int g_group_idx[BQ * SQ * KQ];

// fp16 B-fragments for m16n8k16: uint2 at (kt*128+n)*4+tg:
//   .x = {W[16kt+2tg][n],  W[16kt+2tg+1][n]}   (fp16x2)
//   .y = {W[16kt+2tg+8][n],W[16kt+2tg+9][n]}
// column space is PERMUTED: feats/f' first, xn last (perm baked in here).
__device__ uint2 g_W1h[5 * 512];
__device__ uint2 g_W2h[8 * 512];
__device__ uint2 g_W3h[9 * 512];
__device__ uint2 g_W4h[8 * 512];

__device__ __forceinline__ unsigned f2h2(float lo, float hi) {
    __half2 h = __floats2half2_rn(lo, hi);
    return *(unsigned*)&h;
}
__device__ __forceinline__ void mma_f16(
    float& d0, float& d1, float& d2, float& d3,
    unsigned a0, unsigned a1, unsigned a2, unsigned a3,
    unsigned b0, unsigned b1)
{
    asm("mma.sync.aligned.m16n8k16.row.col.f32.f16.f16.f32 "
        "{%0,%1,%2,%3}, {%4,%5,%6,%7}, {%8,%9}, {%0,%1,%2,%3};"
        : "+f"(d0), "+f"(d1), "+f"(d2), "+f"(d3)
        : "r"(a0), "r"(a1), "r"(a2), "r"(a3), "r"(b0), "r"(b1));
}

// packed f32x2 helpers (FPS)
__device__ __forceinline__ unsigned long long add2(
    unsigned long long a, unsigned long long b)
{
    unsigned long long d;
    asm("add.rn.f32x2 %0, %1, %2;" : "=l"(d) : "l"(a), "l"(b));
    return d;
}
__device__ __forceinline__ unsigned long long mul2(
    unsigned long long a, unsigned long long b)
{
    unsigned long long d;
    asm("mul.rn.f32x2 %0, %1, %2;" : "=l"(d) : "l"(a), "l"(b));
    return d;
}
__device__ __forceinline__ unsigned long long fma2(
    unsigned long long a, unsigned long long b, unsigned long long c)
{
    unsigned long long d;
    asm("fma.rn.f32x2 %0, %1, %2, %3;" : "=l"(d) : "l"(a), "l"(b), "l"(c));
    return d;
}
__device__ __forceinline__ unsigned long long bcast2(float w)
{
    unsigned long long d; unsigned u = __float_as_uint(w);
    asm("mov.b64 %0, {%1, %1};" : "=l"(d) : "r"(u));
    return d;
}
__device__ __forceinline__ float2 unpk2(unsigned long long a)
{
    float2 f;
    asm("mov.b64 {%0, %1}, %2;" : "=f"(f.x), "=f"(f.y) : "l"(a));
    return f;
}

// fragment-major A index for m16n8k16 (word = fp16x2 pair):
// pi = k>>1 (pair index). kt = pi>>3, pp = pi&7,
// ls = (r&7)*4 + (pp&3), reg = ((r>>3)&1) + 2*((pp>>2)&1), mi = r>>4.
__device__ __forceinline__ int pidx16(int r, int pi) {
    int kt = pi >> 3, pp = pi & 7;
    int ls = (r & 7) * 4 + (pp & 3);
    int reg = ((r >> 3) & 1) + 2 * ((pp >> 2) & 1);
    return (((kt * 4 + (r >> 4)) * 32 + ls) << 2) + reg;
}

// ---------------------------------------------------------------------------
// Kernel 0: pack weights into per-thread fp16 B-fragments with column perm.
// mode 0: identity (K=128); mode 1: W1 (feats->rows3..66, xn->rows0..2);
// mode 2: W3 (f'->rows3..130, xn->rows0..2).
// ---------------------------------------------------------------------------
__device__ __forceinline__ float getw(const float* __restrict__ W,
                                      int k, int n, int mode)
{
    int r;
    if (mode == 0)      r = (k < 128) ? k       : -1;
    else if (mode == 1) r = (k < 64)  ? k + 3   : (k < 67  ? k - 64  : -1);
    else                r = (k < 128) ? k + 3   : (k < 131 ? k - 128 : -1);
    return (r >= 0) ? W[r * 128 + n] : 0.f;
}
__device__ __forceinline__ void pack16(int i, int KT, int mode,
                                       const float* __restrict__ W, uint2* out)
{
    if (i < KT * 512) {
        int kt = i >> 9, n = (i & 511) >> 2, tg = i & 3;
        int k0 = 16 * kt + 2 * tg;
        out[i] = make_uint2(
            f2h2(getw(W, k0,     n, mode), getw(W, k0 + 1, n, mode)),
            f2h2(getw(W, k0 + 8, n, mode), getw(W, k0 + 9, n, mode)));
    }
}
__global__ void cvt_w_kernel(const float* __restrict__ W1,
                             const float* __restrict__ W2,
                             const float* __restrict__ W3,
                             const float* __restrict__ W4)
{
    int i = blockIdx.x * 256 + threadIdx.x;
    pack16(i, 5, 1, W1, g_W1h);
    pack16(i, 8, 0, W2, g_W2h);
    pack16(i, 9, 2, W3, g_W3h);
    pack16(i, 8, 0, W4, g_W4h);
}

// ---------------------------------------------------------------------------
// Kernel 1: FPS (unchanged — math must stay bit-identical).
// ---------------------------------------------------------------------------
__global__ __launch_bounds__(512) void fps_kernel(
    const float* __restrict__ xyz, float* __restrict__ new_xyz)
{
    const int b = blockIdx.x;
    const int t = threadIdx.x;
    const int lane = t & 31;
    const int warp = t >> 5;
    extern __shared__ float sm[];
    float* xs = sm;
    float* ys = sm + NQ;
    float* zs = sm + 2 * NQ;
    __shared__ unsigned sv[2][16];
    __shared__ int      si[2][16];

    const float* xb = xyz + (size_t)b * NQ * 3;
    for (int idx = t; idx < NQ * 3; idx += 512) {
        float v = xb[idx];
        int p = idx / 3;
        int j = idx - 3 * p;
        if (j == 0) xs[p] = v; else if (j == 1) ys[p] = v; else zs[p] = v;
    }
    __syncthreads();

    unsigned long long px2[4], py2[4], pz2[4];
    float dmin[8];
#pragma unroll
    for (int q = 0; q < 4; q++) {
        int p0 = t + ((2 * q) << 9), p1 = t + ((2 * q + 1) << 9);
        px2[q] = (unsigned long long)__float_as_uint(xs[p0]) |
                 ((unsigned long long)__float_as_uint(xs[p1]) << 32);
        py2[q] = (unsigned long long)__float_as_uint(ys[p0]) |
                 ((unsigned long long)__float_as_uint(ys[p1]) << 32);
        pz2[q] = (unsigned long long)__float_as_uint(zs[p0]) |
                 ((unsigned long long)__float_as_uint(zs[p1]) << 32);
        dmin[2 * q] = 3.0e38f; dmin[2 * q + 1] = 3.0e38f;
    }
    float cx = xs[0], cy = ys[0], cz = zs[0];
    if (t == 0) {
        float* o = &new_xyz[(size_t)b * SQ * 3];
        o[0] = cx; o[1] = cy; o[2] = cz;
    }

    for (int i = 1; i < SQ; i++) {
        unsigned long long ncx = bcast2(-cx), ncy = bcast2(-cy), ncz = bcast2(-cz);
        unsigned bb[8];
#pragma unroll
        for (int q = 0; q < 4; q++) {
            unsigned long long dx = add2(px2[q], ncx);
            unsigned long long dy = add2(py2[q], ncy);
            unsigned long long dz = add2(pz2[q], ncz);
            unsigned long long d2 = mul2(dx, dx);
            d2 = fma2(dy, dy, d2);
            d2 = fma2(dz, dz, d2);
            float2 f = unpk2(d2);
            float a = fminf(dmin[2 * q], f.x);
            float c = fminf(dmin[2 * q + 1], f.y);
            dmin[2 * q] = a; dmin[2 * q + 1] = c;
            bb[2 * q] = __float_as_uint(a);
            bb[2 * q + 1] = __float_as_uint(c);
        }
        unsigned m01 = max(bb[0], bb[1]), m23 = max(bb[2], bb[3]);
        unsigned m45 = max(bb[4], bb[5]), m67 = max(bb[6], bb[7]);
        unsigned mloc = max(max(m01, m23), max(m45, m67));
        unsigned vmax = __reduce_max_sync(0xffffffffu, mloc);
        unsigned mk = 0;
#pragma unroll
        for (int r = 0; r < 8; r++) mk |= (bb[r] == vmax) ? (1u << r) : 0u;
        int pl = mk ? (t + ((__ffs(mk) - 1) << 9)) : 0x7fffffff;
        int imin = __reduce_min_sync(0xffffffffu, pl);

        const int buf = i & 1;
        if (lane == 0) { sv[buf][warp] = vmax; si[buf][warp] = imin; }
        __syncthreads();
        unsigned vb = sv[buf][lane & 15];
        int      ib = si[buf][lane & 15];
        unsigned vm = __reduce_max_sync(0xffffffffu, vb);
        int c2 = (vb == vm) ? ib : 0x7fffffff;
        int im = __reduce_min_sync(0xffffffffu, c2);
        cx = xs[im]; cy = ys[im]; cz = zs[im];
        if (t == 0) {
            float* o = &new_xyz[((size_t)b * SQ + i) * 3];
            o[0] = cx; o[1] = cy; o[2] = cz;
        }
    }
}

// ---------------------------------------------------------------------------
// Kernel 2: ball query (unchanged).
// ---------------------------------------------------------------------------
__global__ __launch_bounds__(256) void ball_kernel(
    const float* __restrict__ xyz, const float* __restrict__ new_xyz)
{
    const int blk = blockIdx.x;
    const int b = blk >> 7;
    const int t = threadIdx.x;
    const int lane = t & 31;
    const int warp = t >> 5;
    const int s = ((blk & 127) << 3) + warp;

    extern __shared__ float sm[];
    float* xs = sm;
    float* ys = sm + NQ;
    float* zs = sm + 2 * NQ;
    unsigned long long* cand =
        (unsigned long long*)(sm + 3 * NQ) + (size_t)warp * CAND_CAP;

    const float* xb = xyz + (size_t)b * NQ * 3;
    for (int idx = t; idx < NQ * 3; idx += 256) {
        float v = xb[idx];
        int p = idx / 3;
        int j = idx - 3 * p;
        if (j == 0) xs[p] = v; else if (j == 1) ys[p] = v; else zs[p] = v;
    }
    __syncthreads();

    const float* cc = &new_xyz[((size_t)b * SQ + s) * 3];
    const float cx = cc[0], cy = cc[1], cz = cc[2];

    int cnt = 0;
#pragma unroll 4
    for (int j = 0; j < NQ / 32; j++) {
        int p = (j << 5) + lane;
        float dx = xs[p] - cx, dy = ys[p] - cy, dz = zs[p] - cz;
        float d = dx * dx;
        d = fmaf(dy, dy, d);
        d = fmaf(dz, dz, d);
        bool in = (d <= 0.04f);
        unsigned m = __ballot_sync(0xffffffffu, in);
        int pos = cnt + __popc(m & ((1u << lane) - 1u));
        if (in && pos < CAND_CAP)
            cand[pos] = ((unsigned long long)__float_as_uint(d) << 32) |
                        (unsigned)p;
        cnt += __popc(m);
    }
    __syncwarp();
    int L = cnt < CAND_CAP ? cnt : CAND_CAP;

    int* go = &g_group_idx[((size_t)b * SQ + s) * KQ];

    for (int c = lane; c < L; c += 32) {
        unsigned long long key = cand[c];
        int rank = 0;
        for (int j = 0; j < L; j++) rank += (cand[j] < key);
        if (rank < KQ) go[rank] = (int)(unsigned)key;
    }

    if (L < KQ) {
        int fillpos = L;
        for (int base = 0; base < NQ && fillpos < KQ; base += 32) {
            int p = base + lane;
            float dx = xs[p] - cx, dy = ys[p] - cy, dz = zs[p] - cz;
            float d = dx * dx;
            d = fmaf(dy, dy, d);
            d = fmaf(dz, dz, d);
            bool ob = (d > 0.04f);
            unsigned m = __ballot_sync(0xffffffffu, ob);
            int pos = fillpos + __popc(m & ((1u << lane) - 1u));
            if (ob && pos < KQ) go[pos] = p;
            fillpos += __popc(m);
        }
    }
}

// ---------------------------------------------------------------------------
// Kernel 3: fused MLP on fp16 m16n8k16 (fp32 accumulate).
// 256 threads, 8 warps = (wm: m-half) x (wn: 32-ch slice). M=64, 2 centers.
// ---------------------------------------------------------------------------
template<int KT>
__device__ __forceinline__ void gemm_layer(
    const unsigned* __restrict__ P, const uint2* __restrict__ Wp,
    int lane, int g, int tg, int nb, int mibase, float acc[2][4][4])
{
#pragma unroll
    for (int mi = 0; mi < 2; mi++)
#pragma unroll
        for (int nt = 0; nt < 4; nt++)
#pragma unroll
            for (int q = 0; q < 4; q++) acc[mi][nt][q] = 0.f;

#pragma unroll
    for (int kt = 0; kt < KT; kt++) {
        uint4 a[2];
#pragma unroll
        for (int mi = 0; mi < 2; mi++)
            a[mi] = *(const uint4*)&P[(((kt * 4 + mibase + mi) * 32 + lane) << 2)];
#pragma unroll
        for (int nt = 0; nt < 4; nt++) {
            int nc = nb + (nt << 3) + g;
            uint2 bb = __ldg(&Wp[(kt * 128 + nc) * 4 + tg]);
#pragma unroll
            for (int mi = 0; mi < 2; mi++)
                mma_f16(acc[mi][nt][0], acc[mi][nt][1],
                        acc[mi][nt][2], acc[mi][nt][3],
                        a[mi].x, a[mi].y, a[mi].z, a[mi].w, bb.x, bb.y);
        }
    }
}

__global__ __launch_bounds__(256, 3) void mlp_kernel(
    const float* __restrict__ xyz, const float* __restrict__ feats,
    const float* __restrict__ new_xyz,
    const float* __restrict__ b1, const float* __restrict__ b2,
    const float* __restrict__ b3, const float* __restrict__ b4,
    float* __restrict__ f_out)
{
    const int bs0 = blockIdx.x << 1;
    const int b   = bs0 >> 10;
    const int t   = threadIdx.x;
    const int lane = t & 31;
    const int warp = t >> 5;
    const int wm  = warp >> 2;
    const int wn  = warp & 3;
    const int g  = lane >> 2;
    const int tg = lane & 3;
    const int nb = wn << 5;
    const int mibase = wm << 1;

    extern __shared__ unsigned dynsm[];
    unsigned* P    = dynsm;                       // PWORDS
    float*    Fbuf = (float*)(dynsm + PWORDS);    // 64*FS
    float*    xns  = Fbuf + 64 * FS;              // 192
    float*    mb   = xns + 192;                   // 256
    __shared__ int   gi[2 * KQ];
    __shared__ float ctr[6];

    if (t < 2 * KQ) gi[t] = g_group_idx[(size_t)bs0 * KQ + t];
    if (t >= 64 && t < 70) ctr[t - 64] = new_xyz[(size_t)bs0 * 3 + (t - 64)];
    __syncthreads();

    // ---- gather A1 (K=80, permuted): feats pi0-31, xn pi32-33, zero 34-39 ----
    const float* fb = feats + (size_t)b * NQ * CQ;
    for (int e = t; e < 64 * 32; e += 256) {       // 64 rows x 32 ch-pairs
        int r = e >> 5, p = e & 31;
        float2 v = *(const float2*)(fb + (size_t)gi[r] * CQ + 2 * p);
        P[pidx16(r, p)] = f2h2(v.x, v.y);
    }
    if (t < 192) {                                  // xn staging (fp32)
        int r = t % 64, j = t / 64;
        int cen = r >> 5;
        xns[cen * 96 + j * 32 + (r & 31)] =
            xyz[((size_t)b * NQ + gi[r]) * 3 + j] - ctr[cen * 3 + j];
    }
    __syncthreads();
    if (t < 128) {
        int r = t & 63, hi = t >> 6;
        int cen = r >> 5;
        float x0 = xns[cen * 96 +  0 + (r & 31)];
        float x1 = xns[cen * 96 + 32 + (r & 31)];
        float x2 = xns[cen * 96 + 64 + (r & 31)];
        if (hi == 0) P[pidx16(r, 32)] = f2h2(x0, x1);
        else         P[pidx16(r, 33)] = f2h2(x2, 0.f);
    }
    for (int e = t; e < 384; e += 256) {            // zero pads pi 34..39
        int r = e / 6, pi = 34 + e % 6;
        P[pidx16(r, pi)] = 0u;
    }
    __syncthreads();

    float acc[2][4][4];

    // ----- Layer 1: 80(pad) -> 128, relu -----
    gemm_layer<5>(P, g_W1h, lane, g, tg, nb, mibase, acc);
    __syncthreads();
#pragma unroll
    for (int nt = 0; nt < 4; nt++) {
        int cc = nb + (nt << 3) + 2 * tg;
        int pi = cc >> 1;
        float bb0 = __ldg(&b1[cc]), bb1 = __ldg(&b1[cc + 1]);
#pragma unroll
        for (int mi = 0; mi < 2; mi++) {
            int r = (mibase + mi) * 16 + g;
            P[pidx16(r, pi)] = f2h2(fmaxf(acc[mi][nt][0] + bb0, 0.f),
                                    fmaxf(acc[mi][nt][1] + bb1, 0.f));
            P[pidx16(r + 8, pi)] = f2h2(fmaxf(acc[mi][nt][2] + bb0, 0.f),
                                        fmaxf(acc[mi][nt][3] + bb1, 0.f));
        }
    }
    __syncthreads();

    // ----- Layer 2: 128 -> 128, relu -> Fbuf (fp32) -----
    gemm_layer<8>(P, g_W2h, lane, g, tg, nb, mibase, acc);
#pragma unroll
    for (int nt = 0; nt < 4; nt++) {
        int cc = nb + (nt << 3) + 2 * tg;
        float bb0 = __ldg(&b2[cc]), bb1 = __ldg(&b2[cc + 1]);
#pragma unroll
        for (int mi = 0; mi < 2; mi++) {
            int r0 = (mibase + mi) * 16 + g;
            Fbuf[r0 * FS + cc]           = fmaxf(acc[mi][nt][0] + bb0, 0.f);
            Fbuf[r0 * FS + cc + 1]       = fmaxf(acc[mi][nt][1] + bb1, 0.f);
            Fbuf[(r0 + 8) * FS + cc]     = fmaxf(acc[mi][nt][2] + bb0, 0.f);
            Fbuf[(r0 + 8) * FS + cc + 1] = fmaxf(acc[mi][nt][3] + bb1, 0.f);
        }
    }
    __syncthreads();

    // ---- means per center/channel ----
    {
        int cen = t >> 7, ch = t & 127;
        float m = 0.f;
#pragma unroll 8
        for (int r = 0; r < 32; r++) m += Fbuf[(cen * 32 + r) * FS + ch];
        mb[cen * 128 + ch] = m * (1.f / 32.f);
    }
    __syncthreads();

    // ---- A2 (K=144, permuted): f'-mean pi0-63, xn pi64-65, zero 66-71 ----
#pragma unroll
    for (int nt = 0; nt < 4; nt++) {
        int cc = nb + (nt << 3) + 2 * tg;
        int pi = cc >> 1;
        float mc0 = mb[wm * 128 + cc], mc1 = mb[wm * 128 + cc + 1];
#pragma unroll
        for (int mi = 0; mi < 2; mi++) {
            int r = (mibase + mi) * 16 + g;
            P[pidx16(r, pi)] = f2h2(Fbuf[r * FS + cc] - mc0,
                                    Fbuf[r * FS + cc + 1] - mc1);
            P[pidx16(r + 8, pi)] = f2h2(Fbuf[(r + 8) * FS + cc] - mc0,
                                        Fbuf[(r + 8) * FS + cc + 1] - mc1);
        }
    }
    if (t < 128) {
        int r = t & 63, hi = t >> 6;
        int cen = r >> 5;
        float x0 = xns[cen * 96 +  0 + (r & 31)];
        float x1 = xns[cen * 96 + 32 + (r & 31)];
        float x2 = xns[cen * 96 + 64 + (r & 31)];
        if (hi == 0) P[pidx16(r, 64)] = f2h2(x0, x1);
        else         P[pidx16(r, 65)] = f2h2(x2, 0.f);
    }
    for (int e = t; e < 384; e += 256) {
        int r = e / 6, pi = 66 + e % 6;
        P[pidx16(r, pi)] = 0u;
    }
    __syncthreads();

    // ----- Layer 3: 144(pad) -> 128, relu -----
    gemm_layer<9>(P, g_W3h, lane, g, tg, nb, mibase, acc);
    __syncthreads();
#pragma unroll
    for (int nt = 0; nt < 4; nt++) {
        int cc = nb + (nt << 3) + 2 * tg;
        int pi = cc >> 1;
        float bb0 = __ldg(&b3[cc]), bb1 = __ldg(&b3[cc + 1]);
#pragma unroll
        for (int mi = 0; mi < 2; mi++) {
            int r = (mibase + mi) * 16 + g;
            P[pidx16(r, pi)] = f2h2(fmaxf(acc[mi][nt][0] + bb0, 0.f),
                                    fmaxf(acc[mi][nt][1] + bb1, 0.f));
            P[pidx16(r + 8, pi)] = f2h2(fmaxf(acc[mi][nt][2] + bb0, 0.f),
                                        fmaxf(acc[mi][nt][3] + bb1, 0.f));
        }
    }
    __syncthreads();

    // ----- Layer 4: 128 -> 128, sigmoid; weighted sum (center = wm) -----
    gemm_layer<8>(P, g_W4h, lane, g, tg, nb, mibase, acc);
#pragma unroll
    for (int nt = 0; nt < 4; nt++) {
        int cc = nb + (nt << 3) + 2 * tg;
        float bb0 = __ldg(&b4[cc]), bb1 = __ldg(&b4[cc + 1]);
        float s0 = 0.f, s1 = 0.f;
#pragma unroll
        for (int mi = 0; mi < 2; mi++) {
            int r0 = (mibase + mi) * 16 + g;
            float a0 = 1.f / (1.f + __expf(-(acc[mi][nt][0] + bb0)));
            float a1 = 1.f / (1.f + __expf(-(acc[mi][nt][1] + bb1)));
            float a2 = 1.f / (1.f + __expf(-(acc[mi][nt][2] + bb0)));
            float a3 = 1.f / (1.f + __expf(-(acc[mi][nt][3] + bb1)));
            s0 = fmaf(a0, Fbuf[r0 * FS + cc], s0);
            s1 = fmaf(a1, Fbuf[r0 * FS + cc + 1], s1);
            s0 = fmaf(a2, Fbuf[(r0 + 8) * FS + cc], s0);
            s1 = fmaf(a3, Fbuf[(r0 + 8) * FS + cc + 1], s1);
        }
#pragma unroll
        for (int off = 4; off < 32; off <<= 1) {
            s0 += __shfl_xor_sync(0xffffffffu, s0, off);
            s1 += __shfl_xor_sync(0xffffffffu, s1, off);
        }
        if (g == 0) {
            f_out[((size_t)bs0 + wm) * HQ + cc]     = s0;
            f_out[((size_t)bs0 + wm) * HQ + cc + 1] = s1;
        }
    }
}

// ---------------------------------------------------------------------------
extern "C" void kernel_launch(void* const* d_in, const int* in_sizes, int n_in,
                              void* d_out, int out_size)
{
    const float* xyz   = (const float*)d_in[0];
    const float* feats = (const float*)d_in[1];
    const float* W1 = (const float*)d_in[2];
    const float* b1 = (const float*)d_in[3];
    const float* W2 = (const float*)d_in[4];
    const float* b2 = (const float*)d_in[5];
    const float* W3 = (const float*)d_in[6];
    const float* b3 = (const float*)d_in[7];
    const float* W4 = (const float*)d_in[8];
    const float* b4 = (const float*)d_in[9];

    float* out     = (float*)d_out;
    float* new_xyz = out;
    float* f_out   = out + (size_t)BQ * SQ * 3;

    const int fps_smem  = 3 * NQ * sizeof(float);                       // 48KB
    const int ball_smem = fps_smem + 8 * CAND_CAP * sizeof(long long);  // 96KB
    const int mlp_smem  = (PWORDS + 64 * FS + 192 + 256) * 4;           // ~54KB
    cudaFuncSetAttribute(fps_kernel,
                         cudaFuncAttributeMaxDynamicSharedMemorySize, fps_smem);
    cudaFuncSetAttribute(ball_kernel,
                         cudaFuncAttributeMaxDynamicSharedMemorySize, ball_smem);
    cudaFuncSetAttribute(mlp_kernel,
                         cudaFuncAttributeMaxDynamicSharedMemorySize, mlp_smem);

    cvt_w_kernel<<<(9 * 512 + 255) / 256, 256>>>(W1, W2, W3, W4);
    fps_kernel <<<BQ, 512, fps_smem>>>(xyz, new_xyz);
    ball_kernel<<<(BQ * SQ) / 8, 256, ball_smem>>>(xyz, new_xyz);
    mlp_kernel <<<(BQ * SQ) / 2, 256, mlp_smem>>>(xyz, feats, new_xyz,
                                                  b1, b2, b3, b4, f_out);
}

// round 12
// speedup vs baseline: 1.4736x; 1.0012x over previous
#include <cuda_runtime.h>
#include <cuda_fp16.h>
#include <math.h>

#define BQ 16
#define NQ 4096
#define SQ 1024
#define KQ 32
#define CQ 64
#define HQ 128
#define CAND_CAP 768
#define PWORDS 4608   // 9kt * 4mi * 32 lanes * 4 words

__device__ int g_group_idx[BQ * SQ * KQ];

// fp16 B-fragments packed as uint4 (two adjacent nt fragments per thread):
// index = (kt*8 + wn*2 + ntp)*32 + lane;  lane = g*4+tg.
//  .x={W[16kt+2tg][nc0],W[..+1][nc0]} .y={W[..+8][nc0],W[..+9][nc0]}
//  .z/.w same for nc1 = nc0+8.   nc0 = wn*32 + (2*ntp)*8 + g.
// column space PERMUTED: feats/f' first, xn last (baked into packer).
__device__ uint4 g_W1h[5 * 256];
__device__ uint4 g_W2h[8 * 256];
__device__ uint4 g_W3h[9 * 256];
__device__ uint4 g_W4h[8 * 256];

__device__ __forceinline__ unsigned f2h2(float lo, float hi) {
    __half2 h = __floats2half2_rn(lo, hi);
    return *(unsigned*)&h;
}
__device__ __forceinline__ float2 h22f2(unsigned u) {
    __half2 h = *(__half2*)&u;
    return __half22float2(h);
}
__device__ __forceinline__ void mma_f16(
    float& d0, float& d1, float& d2, float& d3,
    unsigned a0, unsigned a1, unsigned a2, unsigned a3,
    unsigned b0, unsigned b1)
{
    asm("mma.sync.aligned.m16n8k16.row.col.f32.f16.f16.f32 "
        "{%0,%1,%2,%3}, {%4,%5,%6,%7}, {%8,%9}, {%0,%1,%2,%3};"
        : "+f"(d0), "+f"(d1), "+f"(d2), "+f"(d3)
        : "r"(a0), "r"(a1), "r"(a2), "r"(a3), "r"(b0), "r"(b1));
}

// packed f32x2 helpers (FPS)
__device__ __forceinline__ unsigned long long add2(
    unsigned long long a, unsigned long long b)
{
    unsigned long long d;
    asm("add.rn.f32x2 %0, %1, %2;" : "=l"(d) : "l"(a), "l"(b));
    return d;
}
__device__ __forceinline__ unsigned long long mul2(
    unsigned long long a, unsigned long long b)
{
    unsigned long long d;
    asm("mul.rn.f32x2 %0, %1, %2;" : "=l"(d) : "l"(a), "l"(b));
    return d;
}
__device__ __forceinline__ unsigned long long fma2(
    unsigned long long a, unsigned long long b, unsigned long long c)
{
    unsigned long long d;
    asm("fma.rn.f32x2 %0, %1, %2, %3;" : "=l"(d) : "l"(a), "l"(b), "l"(c));
    return d;
}
__device__ __forceinline__ unsigned long long bcast2(float w)
{
    unsigned long long d; unsigned u = __float_as_uint(w);
    asm("mov.b64 %0, {%1, %1};" : "=l"(d) : "r"(u));
    return d;
}
__device__ __forceinline__ float2 unpk2(unsigned long long a)
{
    float2 f;
    asm("mov.b64 {%0, %1}, %2;" : "=f"(f.x), "=f"(f.y) : "l"(a));
    return f;
}

// fragment-major A index for m16n8k16 (word = fp16x2 pair):
// pi = k>>1. kt = pi>>3, pp = pi&7, ls = (r&7)*4 + (pp&3),
// reg = ((r>>3)&1) + 2*((pp>>2)&1), mi = r>>4.
__device__ __forceinline__ int pidx16(int r, int pi) {
    int kt = pi >> 3, pp = pi & 7;
    int ls = (r & 7) * 4 + (pp & 3);
    int reg = ((r >> 3) & 1) + 2 * ((pp >> 2) & 1);
    return (((kt * 4 + (r >> 4)) * 32 + ls) << 2) + reg;
}

// ---------------------------------------------------------------------------
// Kernel 0: pack weights into per-thread fp16 uint4 B-fragments w/ col perm.
// mode 0: identity; mode 1: W1 (feats rows3..66, xn rows0..2);
// mode 2: W3 (f' rows3..130, xn rows0..2).
// ---------------------------------------------------------------------------
__device__ __forceinline__ float getw(const float* __restrict__ W,
                                      int k, int n, int mode)
{
    int r;
    if (mode == 0)      r = (k < 128) ? k       : -1;
    else if (mode == 1) r = (k < 64)  ? k + 3   : (k < 67  ? k - 64  : -1);
    else                r = (k < 128) ? k + 3   : (k < 131 ? k - 128 : -1);
    return (r >= 0) ? W[r * 128 + n] : 0.f;
}
__device__ __forceinline__ void pack16(int i, int KT, int mode,
                                       const float* __restrict__ W, uint4* out)
{
    if (i < KT * 256) {
        int kt = i >> 8, rem = i & 255;
        int w = rem >> 5, lane = rem & 31;
        int wn = w >> 1, ntp = w & 1;
        int g = lane >> 2, tg = lane & 3;
        int nc0 = wn * 32 + (2 * ntp) * 8 + g;
        int nc1 = nc0 + 8;
        int k0 = 16 * kt + 2 * tg;
        out[i] = make_uint4(
            f2h2(getw(W, k0,     nc0, mode), getw(W, k0 + 1, nc0, mode)),
            f2h2(getw(W, k0 + 8, nc0, mode), getw(W, k0 + 9, nc0, mode)),
            f2h2(getw(W, k0,     nc1, mode), getw(W, k0 + 1, nc1, mode)),
            f2h2(getw(W, k0 + 8, nc1, mode), getw(W, k0 + 9, nc1, mode)));
    }
}
__global__ void cvt_w_kernel(const float* __restrict__ W1,
                             const float* __restrict__ W2,
                             const float* __restrict__ W3,
                             const float* __restrict__ W4)
{
    int i = blockIdx.x * 256 + threadIdx.x;
    pack16(i, 5, 1, W1, g_W1h);
    pack16(i, 8, 0, W2, g_W2h);
    pack16(i, 9, 2, W3, g_W3h);
    pack16(i, 8, 0, W4, g_W4h);
}

// ---------------------------------------------------------------------------
// Kernel 1: FPS (unchanged — math must stay bit-identical).
// ---------------------------------------------------------------------------
__global__ __launch_bounds__(512) void fps_kernel(
    const float* __restrict__ xyz, float* __restrict__ new_xyz)
{
    const int b = blockIdx.x;
    const int t = threadIdx.x;
    const int lane = t & 31;
    const int warp = t >> 5;
    extern __shared__ float sm[];
    float* xs = sm;
    float* ys = sm + NQ;
    float* zs = sm + 2 * NQ;
    __shared__ unsigned sv[2][16];
    __shared__ int      si[2][16];

    const float* xb = xyz + (size_t)b * NQ * 3;
    for (int idx = t; idx < NQ * 3; idx += 512) {
        float v = xb[idx];
        int p = idx / 3;
        int j = idx - 3 * p;
        if (j == 0) xs[p] = v; else if (j == 1) ys[p] = v; else zs[p] = v;
    }
    __syncthreads();

    unsigned long long px2[4], py2[4], pz2[4];
    float dmin[8];
#pragma unroll
    for (int q = 0; q < 4; q++) {
        int p0 = t + ((2 * q) << 9), p1 = t + ((2 * q + 1) << 9);
        px2[q] = (unsigned long long)__float_as_uint(xs[p0]) |
                 ((unsigned long long)__float_as_uint(xs[p1]) << 32);
        py2[q] = (unsigned long long)__float_as_uint(ys[p0]) |
                 ((unsigned long long)__float_as_uint(ys[p1]) << 32);
        pz2[q] = (unsigned long long)__float_as_uint(zs[p0]) |
                 ((unsigned long long)__float_as_uint(zs[p1]) << 32);
        dmin[2 * q] = 3.0e38f; dmin[2 * q + 1] = 3.0e38f;
    }
    float cx = xs[0], cy = ys[0], cz = zs[0];
    if (t == 0) {
        float* o = &new_xyz[(size_t)b * SQ * 3];
        o[0] = cx; o[1] = cy; o[2] = cz;
    }

    for (int i = 1; i < SQ; i++) {
        unsigned long long ncx = bcast2(-cx), ncy = bcast2(-cy), ncz = bcast2(-cz);
        unsigned bb[8];
#pragma unroll
        for (int q = 0; q < 4; q++) {
            unsigned long long dx = add2(px2[q], ncx);
            unsigned long long dy = add2(py2[q], ncy);
            unsigned long long dz = add2(pz2[q], ncz);
            unsigned long long d2 = mul2(dx, dx);
            d2 = fma2(dy, dy, d2);
            d2 = fma2(dz, dz, d2);
            float2 f = unpk2(d2);
            float a = fminf(dmin[2 * q], f.x);
            float c = fminf(dmin[2 * q + 1], f.y);
            dmin[2 * q] = a; dmin[2 * q + 1] = c;
            bb[2 * q] = __float_as_uint(a);
            bb[2 * q + 1] = __float_as_uint(c);
        }
        unsigned m01 = max(bb[0], bb[1]), m23 = max(bb[2], bb[3]);
        unsigned m45 = max(bb[4], bb[5]), m67 = max(bb[6], bb[7]);
        unsigned mloc = max(max(m01, m23), max(m45, m67));
        unsigned vmax = __reduce_max_sync(0xffffffffu, mloc);
        unsigned mk = 0;
#pragma unroll
        for (int r = 0; r < 8; r++) mk |= (bb[r] == vmax) ? (1u << r) : 0u;
        int pl = mk ? (t + ((__ffs(mk) - 1) << 9)) : 0x7fffffff;
        int imin = __reduce_min_sync(0xffffffffu, pl);

        const int buf = i & 1;
        if (lane == 0) { sv[buf][warp] = vmax; si[buf][warp] = imin; }
        __syncthreads();
        unsigned vb = sv[buf][lane & 15];
        int      ib = si[buf][lane & 15];
        unsigned vm = __reduce_max_sync(0xffffffffu, vb);
        int c2 = (vb == vm) ? ib : 0x7fffffff;
        int im = __reduce_min_sync(0xffffffffu, c2);
        cx = xs[im]; cy = ys[im]; cz = zs[im];
        if (t == 0) {
            float* o = &new_xyz[((size_t)b * SQ + i) * 3];
            o[0] = cx; o[1] = cy; o[2] = cz;
        }
    }
}

// ---------------------------------------------------------------------------
// Kernel 2: ball query (unchanged).
// ---------------------------------------------------------------------------
__global__ __launch_bounds__(256) void ball_kernel(
    const float* __restrict__ xyz, const float* __restrict__ new_xyz)
{
    const int blk = blockIdx.x;
    const int b = blk >> 7;
    const int t = threadIdx.x;
    const int lane = t & 31;
    const int warp = t >> 5;
    const int s = ((blk & 127) << 3) + warp;

    extern __shared__ float sm[];
    float* xs = sm;
    float* ys = sm + NQ;
    float* zs = sm + 2 * NQ;
    unsigned long long* cand =
        (unsigned long long*)(sm + 3 * NQ) + (size_t)warp * CAND_CAP;

    const float* xb = xyz + (size_t)b * NQ * 3;
    for (int idx = t; idx < NQ * 3; idx += 256) {
        float v = xb[idx];
        int p = idx / 3;
        int j = idx - 3 * p;
        if (j == 0) xs[p] = v; else if (j == 1) ys[p] = v; else zs[p] = v;
    }
    __syncthreads();

    const float* cc = &new_xyz[((size_t)b * SQ + s) * 3];
    const float cx = cc[0], cy = cc[1], cz = cc[2];

    int cnt = 0;
#pragma unroll 4
    for (int j = 0; j < NQ / 32; j++) {
        int p = (j << 5) + lane;
        float dx = xs[p] - cx, dy = ys[p] - cy, dz = zs[p] - cz;
        float d = dx * dx;
        d = fmaf(dy, dy, d);
        d = fmaf(dz, dz, d);
        bool in = (d <= 0.04f);
        unsigned m = __ballot_sync(0xffffffffu, in);
        int pos = cnt + __popc(m & ((1u << lane) - 1u));
        if (in && pos < CAND_CAP)
            cand[pos] = ((unsigned long long)__float_as_uint(d) << 32) |
                        (unsigned)p;
        cnt += __popc(m);
    }
    __syncwarp();
    int L = cnt < CAND_CAP ? cnt : CAND_CAP;

    int* go = &g_group_idx[((size_t)b * SQ + s) * KQ];

    for (int c = lane; c < L; c += 32) {
        unsigned long long key = cand[c];
        int rank = 0;
        for (int j = 0; j < L; j++) rank += (cand[j] < key);
        if (rank < KQ) go[rank] = (int)(unsigned)key;
    }

    if (L < KQ) {
        int fillpos = L;
        for (int base = 0; base < NQ && fillpos < KQ; base += 32) {
            int p = base + lane;
            float dx = xs[p] - cx, dy = ys[p] - cy, dz = zs[p] - cz;
            float d = dx * dx;
            d = fmaf(dy, dy, d);
            d = fmaf(dz, dz, d);
            bool ob = (d > 0.04f);
            unsigned m = __ballot_sync(0xffffffffu, ob);
            int pos = fillpos + __popc(m & ((1u << lane) - 1u));
            if (ob && pos < KQ) go[pos] = p;
            fillpos += __popc(m);
        }
    }
}

// ---------------------------------------------------------------------------
// Kernel 3: fused MLP on fp16 m16n8k16. f' kept in REGISTERS (no Fbuf);
// means via g-coset shuffles. Weights as LDG.128 uint4 fragments.
// 256 threads, 8 warps = (wm: center) x (wn: 32-ch slice).
// ---------------------------------------------------------------------------
template<int KT>
__device__ __forceinline__ void gemm_layer(
    const unsigned* __restrict__ P, const uint4* __restrict__ Wp,
    int lane, int wbase, int mibase, float acc[2][4][4])
{
#pragma unroll
    for (int mi = 0; mi < 2; mi++)
#pragma unroll
        for (int nt = 0; nt < 4; nt++)
#pragma unroll
            for (int q = 0; q < 4; q++) acc[mi][nt][q] = 0.f;

#pragma unroll
    for (int kt = 0; kt < KT; kt++) {
        uint4 a[2];
#pragma unroll
        for (int mi = 0; mi < 2; mi++)
            a[mi] = *(const uint4*)&P[(((kt * 4 + mibase + mi) * 32 + lane) << 2)];
        uint4 w01 = __ldg(&Wp[kt * 256 + wbase]);
        uint4 w23 = __ldg(&Wp[kt * 256 + wbase + 32]);
#pragma unroll
        for (int mi = 0; mi < 2; mi++) {
            mma_f16(acc[mi][0][0], acc[mi][0][1], acc[mi][0][2], acc[mi][0][3],
                    a[mi].x, a[mi].y, a[mi].z, a[mi].w, w01.x, w01.y);
            mma_f16(acc[mi][1][0], acc[mi][1][1], acc[mi][1][2], acc[mi][1][3],
                    a[mi].x, a[mi].y, a[mi].z, a[mi].w, w01.z, w01.w);
            mma_f16(acc[mi][2][0], acc[mi][2][1], acc[mi][2][2], acc[mi][2][3],
                    a[mi].x, a[mi].y, a[mi].z, a[mi].w, w23.x, w23.y);
            mma_f16(acc[mi][3][0], acc[mi][3][1], acc[mi][3][2], acc[mi][3][3],
                    a[mi].x, a[mi].y, a[mi].z, a[mi].w, w23.z, w23.w);
        }
    }
}

__global__ __launch_bounds__(256, 3) void mlp_kernel(
    const float* __restrict__ xyz, const float* __restrict__ feats,
    const float* __restrict__ new_xyz,
    const float* __restrict__ b1, const float* __restrict__ b2,
    const float* __restrict__ b3, const float* __restrict__ b4,
    float* __restrict__ f_out)
{
    const int bs0 = blockIdx.x << 1;
    const int b   = bs0 >> 10;
    const int t   = threadIdx.x;
    const int lane = t & 31;
    const int warp = t >> 5;
    const int wm  = warp >> 2;
    const int wn  = warp & 3;
    const int g  = lane >> 2;
    const int tg = lane & 3;
    const int nb = wn << 5;
    const int mibase = wm << 1;
    const int wbase = wn * 64 + lane;

    extern __shared__ unsigned dynsm[];
    unsigned* P   = dynsm;                        // PWORDS
    float*    xns = (float*)(dynsm + PWORDS);     // 192
    __shared__ int   gi[2 * KQ];
    __shared__ float ctr[6];

    if (t < 2 * KQ) gi[t] = g_group_idx[(size_t)bs0 * KQ + t];
    if (t >= 64 && t < 70) ctr[t - 64] = new_xyz[(size_t)bs0 * 3 + (t - 64)];
    __syncthreads();

    // ---- gather A1 (K=80, permuted): feats pi0-31, xn pi32-33, zero 34-39 ----
    const float* fb = feats + (size_t)b * NQ * CQ;
    for (int e = t; e < 64 * 32; e += 256) {
        int r = e >> 5, p = e & 31;
        float2 v = *(const float2*)(fb + (size_t)gi[r] * CQ + 2 * p);
        P[pidx16(r, p)] = f2h2(v.x, v.y);
    }
    if (t < 192) {
        int r = t % 64, j = t / 64;
        int cen = r >> 5;
        xns[cen * 96 + j * 32 + (r & 31)] =
            xyz[((size_t)b * NQ + gi[r]) * 3 + j] - ctr[cen * 3 + j];
    }
    __syncthreads();
    if (t < 128) {
        int r = t & 63, hi = t >> 6;
        int cen = r >> 5;
        float x0 = xns[cen * 96 +  0 + (r & 31)];
        float x1 = xns[cen * 96 + 32 + (r & 31)];
        float x2 = xns[cen * 96 + 64 + (r & 31)];
        if (hi == 0) P[pidx16(r, 32)] = f2h2(x0, x1);
        else         P[pidx16(r, 33)] = f2h2(x2, 0.f);
    }
    for (int e = t; e < 384; e += 256) {
        int r = e / 6, pi = 34 + e % 6;
        P[pidx16(r, pi)] = 0u;
    }
    __syncthreads();

    float acc[2][4][4];

    // ----- Layer 1: 80(pad) -> 128, relu -----
    gemm_layer<5>(P, g_W1h, lane, wbase, mibase, acc);
    __syncthreads();
#pragma unroll
    for (int nt = 0; nt < 4; nt++) {
        int cc = nb + (nt << 3) + 2 * tg;
        int pi = cc >> 1;
        float bb0 = __ldg(&b1[cc]), bb1 = __ldg(&b1[cc + 1]);
#pragma unroll
        for (int mi = 0; mi < 2; mi++) {
            int r = (mibase + mi) * 16 + g;
            P[pidx16(r, pi)] = f2h2(fmaxf(acc[mi][nt][0] + bb0, 0.f),
                                    fmaxf(acc[mi][nt][1] + bb1, 0.f));
            P[pidx16(r + 8, pi)] = f2h2(fmaxf(acc[mi][nt][2] + bb0, 0.f),
                                        fmaxf(acc[mi][nt][3] + bb1, 0.f));
        }
    }
    __syncthreads();

    // ----- Layer 2: 128 -> 128, relu -> f' in REGISTERS (half2 pairs) -----
    gemm_layer<8>(P, g_W2h, lane, wbase, mibase, acc);
    unsigned fpk[2][4][2];
    float2   cm[4];
#pragma unroll
    for (int nt = 0; nt < 4; nt++) {
        int cc = nb + (nt << 3) + 2 * tg;
        float bb0 = __ldg(&b2[cc]), bb1 = __ldg(&b2[cc + 1]);
        float2 cs = make_float2(0.f, 0.f);
#pragma unroll
        for (int mi = 0; mi < 2; mi++) {
            fpk[mi][nt][0] = f2h2(fmaxf(acc[mi][nt][0] + bb0, 0.f),
                                  fmaxf(acc[mi][nt][1] + bb1, 0.f));
            fpk[mi][nt][1] = f2h2(fmaxf(acc[mi][nt][2] + bb0, 0.f),
                                  fmaxf(acc[mi][nt][3] + bb1, 0.f));
            float2 f0 = h22f2(fpk[mi][nt][0]);
            float2 f1 = h22f2(fpk[mi][nt][1]);
            cs.x += f0.x + f1.x;
            cs.y += f0.y + f1.y;
        }
        // reduce over g-coset (lanes tg, tg+4, ..., tg+28)
#pragma unroll
        for (int off = 4; off < 32; off <<= 1) {
            cs.x += __shfl_xor_sync(0xffffffffu, cs.x, off);
            cs.y += __shfl_xor_sync(0xffffffffu, cs.y, off);
        }
        cm[nt] = make_float2(cs.x * (1.f / 32.f), cs.y * (1.f / 32.f));
    }
    __syncthreads();   // all L2 gemm reads of P done -> safe to overwrite

    // ---- A2 (K=144, permuted): f'-mean pi0-63, xn pi64-65, zero 66-71 ----
#pragma unroll
    for (int nt = 0; nt < 4; nt++) {
        int cc = nb + (nt << 3) + 2 * tg;
        int pi = cc >> 1;
#pragma unroll
        for (int mi = 0; mi < 2; mi++) {
            int r = (mibase + mi) * 16 + g;
            float2 f0 = h22f2(fpk[mi][nt][0]);
            float2 f1 = h22f2(fpk[mi][nt][1]);
            P[pidx16(r, pi)]     = f2h2(f0.x - cm[nt].x, f0.y - cm[nt].y);
            P[pidx16(r + 8, pi)] = f2h2(f1.x - cm[nt].x, f1.y - cm[nt].y);
        }
    }
    if (t < 128) {
        int r = t & 63, hi = t >> 6;
        int cen = r >> 5;
        float x0 = xns[cen * 96 +  0 + (r & 31)];
        float x1 = xns[cen * 96 + 32 + (r & 31)];
        float x2 = xns[cen * 96 + 64 + (r & 31)];
        if (hi == 0) P[pidx16(r, 64)] = f2h2(x0, x1);
        else         P[pidx16(r, 65)] = f2h2(x2, 0.f);
    }
    for (int e = t; e < 384; e += 256) {
        int r = e / 6, pi = 66 + e % 6;
        P[pidx16(r, pi)] = 0u;
    }
    __syncthreads();

    // ----- Layer 3: 144(pad) -> 128, relu -----
    gemm_layer<9>(P, g_W3h, lane, wbase, mibase, acc);
    __syncthreads();
#pragma unroll
    for (int nt = 0; nt < 4; nt++) {
        int cc = nb + (nt << 3) + 2 * tg;
        int pi = cc >> 1;
        float bb0 = __ldg(&b3[cc]), bb1 = __ldg(&b3[cc + 1]);
#pragma unroll
        for (int mi = 0; mi < 2; mi++) {
            int r = (mibase + mi) * 16 + g;
            P[pidx16(r, pi)] = f2h2(fmaxf(acc[mi][nt][0] + bb0, 0.f),
                                    fmaxf(acc[mi][nt][1] + bb1, 0.f));
            P[pidx16(r + 8, pi)] = f2h2(fmaxf(acc[mi][nt][2] + bb0, 0.f),
                                        fmaxf(acc[mi][nt][3] + bb1, 0.f));
        }
    }
    __syncthreads();

    // ----- Layer 4: 128 -> 128, sigmoid; weighted sum from fpk regs -----
    gemm_layer<8>(P, g_W4h, lane, wbase, mibase, acc);
#pragma unroll
    for (int nt = 0; nt < 4; nt++) {
        int cc = nb + (nt << 3) + 2 * tg;
        float bb0 = __ldg(&b4[cc]), bb1 = __ldg(&b4[cc + 1]);
        float s0 = 0.f, s1 = 0.f;
#pragma unroll
        for (int mi = 0; mi < 2; mi++) {
            float2 f0 = h22f2(fpk[mi][nt][0]);
            float2 f1 = h22f2(fpk[mi][nt][1]);
            float a0 = 1.f / (1.f + __expf(-(acc[mi][nt][0] + bb0)));
            float a1 = 1.f / (1.f + __expf(-(acc[mi][nt][1] + bb1)));
            float a2 = 1.f / (1.f + __expf(-(acc[mi][nt][2] + bb0)));
            float a3 = 1.f / (1.f + __expf(-(acc[mi][nt][3] + bb1)));
            s0 = fmaf(a0, f0.x, s0);
            s1 = fmaf(a1, f0.y, s1);
            s0 = fmaf(a2, f1.x, s0);
            s1 = fmaf(a3, f1.y, s1);
        }
#pragma unroll
        for (int off = 4; off < 32; off <<= 1) {
            s0 += __shfl_xor_sync(0xffffffffu, s0, off);
            s1 += __shfl_xor_sync(0xffffffffu, s1, off);
        }
        if (g == 0) {
            f_out[((size_t)bs0 + wm) * HQ + cc]     = s0;
            f_out[((size_t)bs0 + wm) * HQ + cc + 1] = s1;
        }
    }
}

// ---------------------------------------------------------------------------
extern "C" void kernel_launch(void* const* d_in, const int* in_sizes, int n_in,
                              void* d_out, int out_size)
{
    const float* xyz   = (const float*)d_in[0];
    const float* feats = (const float*)d_in[1];
    const float* W1 = (const float*)d_in[2];
    const float* b1 = (const float*)d_in[3];
    const float* W2 = (const float*)d_in[4];
    const float* b2 = (const float*)d_in[5];
    const float* W3 = (const float*)d_in[6];
    const float* b3 = (const float*)d_in[7];
    const float* W4 = (const float*)d_in[8];
    const float* b4 = (const float*)d_in[9];

    float* out     = (float*)d_out;
    float* new_xyz = out;
    float* f_out   = out + (size_t)BQ * SQ * 3;

    const int fps_smem  = 3 * NQ * sizeof(float);                       // 48KB
    const int ball_smem = fps_smem + 8 * CAND_CAP * sizeof(long long);  // 96KB
    const int mlp_smem  = (PWORDS + 192) * 4;                           // ~19KB
    cudaFuncSetAttribute(fps_kernel,
                         cudaFuncAttributeMaxDynamicSharedMemorySize, fps_smem);
    cudaFuncSetAttribute(ball_kernel,
                         cudaFuncAttributeMaxDynamicSharedMemorySize, ball_smem);
    cudaFuncSetAttribute(mlp_kernel,
                         cudaFuncAttributeMaxDynamicSharedMemorySize, mlp_smem);

    cvt_w_kernel<<<(9 * 256 + 255) / 256, 256>>>(W1, W2, W3, W4);
    fps_kernel <<<BQ, 512, fps_smem>>>(xyz, new_xyz);
    ball_kernel<<<(BQ * SQ) / 8, 256, ball_smem>>>(xyz, new_xyz);
    mlp_kernel <<<(BQ * SQ) / 2, 256, mlp_smem>>>(xyz, feats, new_xyz,
                                                  b1, b2, b3, b4, f_out);
}